// round 1
// baseline (speedup 1.0000x reference)
#include <cuda_runtime.h>

#define N_NODES_MAX 100000
#define IN_C 300
#define OUT_C 200
#define E_MAX 1600000
#define ETOT_MAX (E_MAX + N_NODES_MAX)
#define NEG_SLOPE 0.2f

// ---------------- scratch (device globals; no allocation allowed) ----------
__device__ float g_h[(size_t)N_NODES_MAX * OUT_C];    // projected features
__device__ float g_out[(size_t)N_NODES_MAX * OUT_C];  // layer-1 aggregation
__device__ float g_as[N_NODES_MAX];
__device__ float g_ad[N_NODES_MAX];
__device__ float g_m[N_NODES_MAX];
__device__ float g_s[N_NODES_MAX];
__device__ float g_e[ETOT_MAX];
__device__ int   g_idx64;   // 1 if edge_index is int64, 0 if int32

// ---------------- helpers ----------------
__device__ __forceinline__ int edge_at(const void* ei, int is64, long long pos) {
    if (is64) return (int)((const long long*)ei)[pos];
    return ((const int*)ei)[pos];
}

__device__ __forceinline__ void atomicMaxF(float* addr, float val) {
    if (val >= 0.f)
        atomicMax((int*)addr, __float_as_int(val));
    else
        atomicMin((unsigned int*)addr, __float_as_uint(val));
}

// Probe edge_index dtype: int64 values < 2^31 have zero high words at odd
// int32 positions; a real int32 edge array has random values there.
__global__ void probe_kernel(const int* ei) {
    if (threadIdx.x == 0 && blockIdx.x == 0) {
        int is64 = 1;
        #pragma unroll
        for (int i = 1; i < 32; i += 2)
            if (ei[i] != 0) { is64 = 0; break; }
        g_idx64 = is64;
    }
}

// ---------------- GEMM: g_h[M,200] = act(A[M,K]) @ W[K,200] ----------------
// BM=64, BN=50, BK=10, 160 threads, 4x5 micro-tile per thread.
template<bool RELU_IN>
__global__ void gemm_kernel(const float* __restrict__ A,
                            const float* __restrict__ W,
                            int M, int K) {
    const int BM = 64, BN = 50, BK = 10, TM = 4, TN = 5;
    __shared__ float sA[BK][BM];
    __shared__ float sB[BK][BN];
    int tid = threadIdx.x;              // 160
    int tx = tid % 10;                  // 10 col groups * TN=5 -> 50
    int ty = tid / 10;                  // 16 row groups * TM=4 -> 64
    int m0 = blockIdx.x * BM;
    int n0 = blockIdx.y * BN;
    float acc[TM][TN];
    #pragma unroll
    for (int i = 0; i < TM; i++)
        #pragma unroll
        for (int j = 0; j < TN; j++) acc[i][j] = 0.f;

    for (int k0 = 0; k0 < K; k0 += BK) {
        for (int idx = tid; idx < BM * BK; idx += 160) {
            int mm = idx / BK, kk = idx % BK;
            int m = m0 + mm;
            float v = (m < M) ? A[(size_t)m * K + k0 + kk] : 0.f;
            if (RELU_IN) v = fmaxf(v, 0.f);
            sA[kk][mm] = v;
        }
        for (int idx = tid; idx < BK * BN; idx += 160) {
            int kk = idx / BN, nn = idx % BN;
            sB[kk][nn] = W[(size_t)(k0 + kk) * OUT_C + n0 + nn];
        }
        __syncthreads();
        #pragma unroll
        for (int kk = 0; kk < BK; kk++) {
            float ra[TM], rb[TN];
            #pragma unroll
            for (int i = 0; i < TM; i++) ra[i] = sA[kk][ty * TM + i];
            #pragma unroll
            for (int j = 0; j < TN; j++) rb[j] = sB[kk][tx * TN + j];
            #pragma unroll
            for (int i = 0; i < TM; i++)
                #pragma unroll
                for (int j = 0; j < TN; j++)
                    acc[i][j] = fmaf(ra[i], rb[j], acc[i][j]);
        }
        __syncthreads();
    }
    #pragma unroll
    for (int i = 0; i < TM; i++) {
        int m = m0 + ty * TM + i;
        if (m >= M) continue;
        #pragma unroll
        for (int j = 0; j < TN; j++)
            g_h[(size_t)m * OUT_C + n0 + tx * TN + j] = acc[i][j];
    }
}

// ---------------- alpha_src / alpha_dst: one warp per node ----------------
__global__ void alpha_kernel(const float* __restrict__ a_src,
                             const float* __restrict__ a_dst, int n) {
    int warp = (int)((blockIdx.x * (size_t)blockDim.x + threadIdx.x) >> 5);
    int lane = threadIdx.x & 31;
    if (warp >= n) return;
    const float4* hr  = (const float4*)(g_h + (size_t)warp * OUT_C);
    const float4* as4 = (const float4*)a_src;
    const float4* ad4 = (const float4*)a_dst;
    float s = 0.f, d = 0.f;
    for (int c = lane; c < OUT_C / 4; c += 32) {
        float4 hv = hr[c], av = as4[c], dv = ad4[c];
        s += hv.x * av.x + hv.y * av.y + hv.z * av.z + hv.w * av.w;
        d += hv.x * dv.x + hv.y * dv.y + hv.z * dv.z + hv.w * dv.w;
    }
    #pragma unroll
    for (int o = 16; o; o >>= 1) {
        s += __shfl_down_sync(0xffffffffu, s, o);
        d += __shfl_down_sync(0xffffffffu, d, o);
    }
    if (lane == 0) { g_as[warp] = s; g_ad[warp] = d; }
}

// ---------------- init: out = bias broadcast, m = -inf, s = 0 --------------
__global__ void init_kernel(float* __restrict__ out,
                            const float* __restrict__ b, int n) {
    int i = blockIdx.x * blockDim.x + threadIdx.x;
    int total = n * OUT_C;
    if (i < total) out[i] = b[i % OUT_C];
    if (i < n) { g_m[i] = -1e30f; g_s[i] = 0.f; }
}

// ---------------- edge pass 1: e = leakyrelu, segment max ------------------
__global__ void edge_max_kernel(const void* __restrict__ ei, int E, int Etot) {
    int i = blockIdx.x * blockDim.x + threadIdx.x;
    if (i >= Etot) return;
    int is64 = g_idx64;
    int src, dst;
    if (i < E) {
        src = edge_at(ei, is64, i);
        dst = edge_at(ei, is64, (long long)E + i);
    } else {
        src = dst = i - E;
    }
    float e = g_as[src] + g_ad[dst];
    e = (e > 0.f) ? e : NEG_SLOPE * e;
    g_e[i] = e;
    atomicMaxF(&g_m[dst], e);
}

// ---------------- edge pass 2: ex = exp(e - m), segment sum ----------------
__global__ void edge_sum_kernel(const void* __restrict__ ei, int E, int Etot) {
    int i = blockIdx.x * blockDim.x + threadIdx.x;
    if (i >= Etot) return;
    int is64 = g_idx64;
    int dst;
    if (i < E) dst = edge_at(ei, is64, (long long)E + i);
    else       dst = i - E;
    float ex = __expf(g_e[i] - g_m[dst]);
    g_e[i] = ex;
    atomicAdd(&g_s[dst], ex);
}

// ---------------- edge pass 3: out[dst] += alpha * h[src] (warp/edge) ------
__global__ void edge_agg_kernel(const void* __restrict__ ei, int E, int Etot,
                                float* __restrict__ out) {
    int warp = (int)((blockIdx.x * (size_t)blockDim.x + threadIdx.x) >> 5);
    int lane = threadIdx.x & 31;
    if (warp >= Etot) return;
    int is64 = g_idx64;
    int src, dst;
    if (warp < E) {
        src = edge_at(ei, is64, warp);
        dst = edge_at(ei, is64, (long long)E + warp);
    } else {
        src = dst = warp - E;
    }
    float alpha = g_e[warp] / g_s[dst];
    const float4* hs = (const float4*)(g_h + (size_t)src * OUT_C);
    float4* op = (float4*)(out + (size_t)dst * OUT_C);
    for (int c = lane; c < OUT_C / 4; c += 32) {
        float4 v = hs[c];
        asm volatile(
            "red.global.add.v4.f32 [%0], {%1, %2, %3, %4};"
            :: "l"(op + c),
               "f"(v.x * alpha), "f"(v.y * alpha),
               "f"(v.z * alpha), "f"(v.w * alpha)
            : "memory");
    }
}

// ---------------- final relu (in place) -------------------------------------
__global__ void relu_kernel(float* __restrict__ p, int total) {
    int i = blockIdx.x * blockDim.x + threadIdx.x;
    if (i < total) p[i] = fmaxf(p[i], 0.f);
}

// ---------------- launch -----------------------------------------------------
extern "C" void kernel_launch(void* const* d_in, const int* in_sizes, int n_in,
                              void* d_out, int out_size) {
    const float* x      = (const float*)d_in[0];
    const float* W0     = (const float*)d_in[1];
    const float* a_src0 = (const float*)d_in[2];
    const float* a_dst0 = (const float*)d_in[3];
    const float* b0     = (const float*)d_in[4];
    const float* W1     = (const float*)d_in[5];
    const float* a_src1 = (const float*)d_in[6];
    const float* a_dst1 = (const float*)d_in[7];
    const float* b1     = (const float*)d_in[8];
    const void*  ei     = d_in[9];

    int n    = in_sizes[0] / IN_C;   // 100000
    int E    = in_sizes[9] / 2;      // 1600000
    int Etot = E + n;

    float* out1;
    cudaGetSymbolAddress((void**)&out1, g_out);

    int total = n * OUT_C;
    dim3 gemm_block(160);
    dim3 gemm_grid((n + 63) / 64, (OUT_C + 49) / 50);
    int init_blocks  = (total + 255) / 256;
    int alpha_blocks = (n * 32 + 255) / 256;
    int edge_blocks  = (Etot + 255) / 256;
    int agg_blocks   = ((size_t)Etot * 32 + 255) / 256;

    probe_kernel<<<1, 32>>>((const int*)ei);

    // ----- layer 1 -----
    gemm_kernel<false><<<gemm_grid, gemm_block>>>(x, W0, n, IN_C);
    alpha_kernel<<<alpha_blocks, 256>>>(a_src0, a_dst0, n);
    init_kernel<<<init_blocks, 256>>>(out1, b0, n);
    edge_max_kernel<<<edge_blocks, 256>>>(ei, E, Etot);
    edge_sum_kernel<<<edge_blocks, 256>>>(ei, E, Etot);
    edge_agg_kernel<<<agg_blocks, 256>>>(ei, E, Etot, out1);

    // ----- layer 2 (relu applied on GEMM input load; final relu on output) --
    gemm_kernel<true><<<gemm_grid, gemm_block>>>(out1, W1, n, OUT_C);
    alpha_kernel<<<alpha_blocks, 256>>>(a_src1, a_dst1, n);
    init_kernel<<<init_blocks, 256>>>((float*)d_out, b1, n);
    edge_max_kernel<<<edge_blocks, 256>>>(ei, E, Etot);
    edge_sum_kernel<<<edge_blocks, 256>>>(ei, E, Etot);
    edge_agg_kernel<<<agg_blocks, 256>>>(ei, E, Etot, (float*)d_out);

    relu_kernel<<<init_blocks, 256>>>((float*)d_out, total);
}

// round 2
// speedup vs baseline: 1.1098x; 1.1098x over previous
#include <cuda_runtime.h>

#define N_NODES_MAX 100000
#define IN_C 300
#define OUT_C 200
#define E_MAX 1600000
#define ETOT_MAX (E_MAX + N_NODES_MAX)
#define NEG_SLOPE 0.2f

// ---------------- scratch (device globals; no allocation allowed) ----------
__device__ float g_h[(size_t)N_NODES_MAX * OUT_C];    // projected features
__device__ float g_out[(size_t)N_NODES_MAX * OUT_C];  // layer-1 aggregation
__device__ float g_as[N_NODES_MAX];
__device__ float g_ad[N_NODES_MAX];
__device__ float g_s[N_NODES_MAX];
__device__ float g_e[ETOT_MAX];
__device__ int   g_idx64;   // 1 if edge_index is int64, 0 if int32

// ---------------- helpers ----------------
__device__ __forceinline__ int edge_at(const void* ei, int is64, long long pos) {
    if (is64) return (int)((const long long*)ei)[pos];
    return ((const int*)ei)[pos];
}

// Probe edge_index dtype: int64 values < 2^31 have zero high words at odd
// int32 positions; a real int32 edge array has random values there.
__global__ void probe_kernel(const int* ei) {
    if (threadIdx.x == 0 && blockIdx.x == 0) {
        int is64 = 1;
        #pragma unroll
        for (int i = 1; i < 32; i += 2)
            if (ei[i] != 0) { is64 = 0; break; }
        g_idx64 = is64;
    }
}

// ---------------- GEMM: g_h[M,200] = act(A[M,K]) @ W[K,200] ----------------
// BM=256, BN=50, BK=20, 320 threads, 8x5 micro-tile per thread.
template<bool RELU_IN>
__global__ __launch_bounds__(320)
void gemm_kernel(const float* __restrict__ A,
                 const float* __restrict__ W,
                 int M, int K) {
    const int BM = 256, BN = 50, BK = 20, TM = 8, TN = 5;
    __shared__ float sA[BK][BM];
    __shared__ float sB[BK][BN];
    int tid = threadIdx.x;              // 320
    int tx = tid % 10;                  // 10 col groups * TN=5 -> 50
    int ty = tid / 10;                  // 32 row groups * TM=8 -> 256
    int m0 = blockIdx.x * BM;
    int n0 = blockIdx.y * BN;
    float acc[TM][TN];
    #pragma unroll
    for (int i = 0; i < TM; i++)
        #pragma unroll
        for (int j = 0; j < TN; j++) acc[i][j] = 0.f;

    for (int k0 = 0; k0 < K; k0 += BK) {
        // A tile: 256 rows x 20 cols = 1280 float4 loads over 320 threads
        #pragma unroll
        for (int r = 0; r < 4; r++) {
            int idx = tid + r * 320;          // 0..1279
            int mm = idx / 5;                 // row in tile
            int vec = idx % 5;                // which float4 within the row
            int m = m0 + mm;
            float4 v = make_float4(0.f, 0.f, 0.f, 0.f);
            if (m < M)
                v = *(const float4*)(A + (size_t)m * K + k0 + vec * 4);
            if (RELU_IN) {
                v.x = fmaxf(v.x, 0.f); v.y = fmaxf(v.y, 0.f);
                v.z = fmaxf(v.z, 0.f); v.w = fmaxf(v.w, 0.f);
            }
            sA[vec * 4 + 0][mm] = v.x;
            sA[vec * 4 + 1][mm] = v.y;
            sA[vec * 4 + 2][mm] = v.z;
            sA[vec * 4 + 3][mm] = v.w;
        }
        // B tile: 20 x 50 = 1000 scalar loads
        for (int idx = tid; idx < BK * BN; idx += 320) {
            int kk = idx / BN, nn = idx % BN;
            sB[kk][nn] = W[(size_t)(k0 + kk) * OUT_C + n0 + nn];
        }
        __syncthreads();
        #pragma unroll
        for (int kk = 0; kk < BK; kk++) {
            float ra[TM], rb[TN];
            #pragma unroll
            for (int i = 0; i < TM; i++) ra[i] = sA[kk][ty * TM + i];
            #pragma unroll
            for (int j = 0; j < TN; j++) rb[j] = sB[kk][tx * TN + j];
            #pragma unroll
            for (int i = 0; i < TM; i++)
                #pragma unroll
                for (int j = 0; j < TN; j++)
                    acc[i][j] = fmaf(ra[i], rb[j], acc[i][j]);
        }
        __syncthreads();
    }
    #pragma unroll
    for (int i = 0; i < TM; i++) {
        int m = m0 + ty * TM + i;
        if (m >= M) continue;
        #pragma unroll
        for (int j = 0; j < TN; j++)
            g_h[(size_t)m * OUT_C + n0 + tx * TN + j] = acc[i][j];
    }
}

// ---------------- alpha_src / alpha_dst: one warp per node ----------------
__global__ void alpha_kernel(const float* __restrict__ a_src,
                             const float* __restrict__ a_dst, int n) {
    int warp = (int)((blockIdx.x * (size_t)blockDim.x + threadIdx.x) >> 5);
    int lane = threadIdx.x & 31;
    if (warp >= n) return;
    const float4* hr  = (const float4*)(g_h + (size_t)warp * OUT_C);
    const float4* as4 = (const float4*)a_src;
    const float4* ad4 = (const float4*)a_dst;
    float s = 0.f, d = 0.f;
    for (int c = lane; c < OUT_C / 4; c += 32) {
        float4 hv = hr[c], av = as4[c], dv = ad4[c];
        s += hv.x * av.x + hv.y * av.y + hv.z * av.z + hv.w * av.w;
        d += hv.x * dv.x + hv.y * dv.y + hv.z * dv.z + hv.w * dv.w;
    }
    #pragma unroll
    for (int o = 16; o; o >>= 1) {
        s += __shfl_down_sync(0xffffffffu, s, o);
        d += __shfl_down_sync(0xffffffffu, d, o);
    }
    if (lane == 0) { g_as[warp] = s; g_ad[warp] = d; }
}

// ---------------- init: out = bias broadcast, s = 0 ------------------------
__global__ void init_kernel(float* __restrict__ out,
                            const float* __restrict__ b, int n) {
    int i = blockIdx.x * blockDim.x + threadIdx.x;
    int total = n * OUT_C;
    if (i < total) out[i] = b[i % OUT_C];
    if (i < n) g_s[i] = 0.f;
}

// ---------------- fused edge pass: ex = exp(leakyrelu(e)), segment sum -----
// No max subtraction needed: e = a_src+a_dst is bounded (|e| << 88), and
// alpha = ex/sum(ex) is algebraically identical to the max-shifted form.
__global__ void edge_expsum_kernel(const void* __restrict__ ei, int E, int Etot) {
    int i = blockIdx.x * blockDim.x + threadIdx.x;
    if (i >= Etot) return;
    int is64 = g_idx64;
    int src, dst;
    if (i < E) {
        src = edge_at(ei, is64, i);
        dst = edge_at(ei, is64, (long long)E + i);
    } else {
        src = dst = i - E;
    }
    float e = __ldg(&g_as[src]) + __ldg(&g_ad[dst]);
    e = (e > 0.f) ? e : NEG_SLOPE * e;
    float ex = __expf(e);
    g_e[i] = ex;
    atomicAdd(&g_s[dst], ex);
}

// ---------------- reciprocal: g_s = 1 / g_s --------------------------------
__global__ void recip_kernel(int n) {
    int i = blockIdx.x * blockDim.x + threadIdx.x;
    if (i < n) g_s[i] = __frcp_rn(g_s[i]);
}

// ---------------- edge agg: out[dst] += alpha * h[src] (warp/edge) ---------
__global__ void edge_agg_kernel(const void* __restrict__ ei, int E, int Etot,
                                float* __restrict__ out) {
    int warp = (int)((blockIdx.x * (size_t)blockDim.x + threadIdx.x) >> 5);
    int lane = threadIdx.x & 31;
    if (warp >= Etot) return;
    int is64 = g_idx64;
    int src, dst;
    if (warp < E) {
        src = edge_at(ei, is64, warp);
        dst = edge_at(ei, is64, (long long)E + warp);
    } else {
        src = dst = warp - E;
    }
    float alpha = g_e[warp] * __ldg(&g_s[dst]);
    const float4* hs = (const float4*)(g_h + (size_t)src * OUT_C);
    float4* op = (float4*)(out + (size_t)dst * OUT_C);
    for (int c = lane; c < OUT_C / 4; c += 32) {
        float4 v = __ldg(hs + c);
        asm volatile(
            "red.global.add.v4.f32 [%0], {%1, %2, %3, %4};"
            :: "l"(op + c),
               "f"(v.x * alpha), "f"(v.y * alpha),
               "f"(v.z * alpha), "f"(v.w * alpha)
            : "memory");
    }
}

// ---------------- final relu (in place) -------------------------------------
__global__ void relu_kernel(float* __restrict__ p, int total) {
    int i = blockIdx.x * blockDim.x + threadIdx.x;
    if (i < total) p[i] = fmaxf(p[i], 0.f);
}

// ---------------- launch -----------------------------------------------------
extern "C" void kernel_launch(void* const* d_in, const int* in_sizes, int n_in,
                              void* d_out, int out_size) {
    const float* x      = (const float*)d_in[0];
    const float* W0     = (const float*)d_in[1];
    const float* a_src0 = (const float*)d_in[2];
    const float* a_dst0 = (const float*)d_in[3];
    const float* b0     = (const float*)d_in[4];
    const float* W1     = (const float*)d_in[5];
    const float* a_src1 = (const float*)d_in[6];
    const float* a_dst1 = (const float*)d_in[7];
    const float* b1     = (const float*)d_in[8];
    const void*  ei     = d_in[9];

    int n    = in_sizes[0] / IN_C;   // 100000
    int E    = in_sizes[9] / 2;      // 1600000
    int Etot = E + n;

    float* out1;
    cudaGetSymbolAddress((void**)&out1, g_out);

    int total = n * OUT_C;
    dim3 gemm_block(320);
    dim3 gemm_grid((n + 255) / 256, (OUT_C + 49) / 50);
    int init_blocks  = (total + 255) / 256;
    int alpha_blocks = (n * 32 + 255) / 256;
    int edge_blocks  = (Etot + 511) / 512;
    int recip_blocks = (n + 255) / 256;
    long long agg_threads = (long long)Etot * 32;
    int agg_blocks   = (int)((agg_threads + 511) / 512);

    probe_kernel<<<1, 32>>>((const int*)ei);

    // ----- layer 1 -----
    gemm_kernel<false><<<gemm_grid, gemm_block>>>(x, W0, n, IN_C);
    alpha_kernel<<<alpha_blocks, 256>>>(a_src0, a_dst0, n);
    init_kernel<<<init_blocks, 256>>>(out1, b0, n);
    edge_expsum_kernel<<<edge_blocks, 512>>>(ei, E, Etot);
    recip_kernel<<<recip_blocks, 256>>>(n);
    edge_agg_kernel<<<agg_blocks, 512>>>(ei, E, Etot, out1);

    // ----- layer 2 (relu applied on GEMM input load; final relu on output) --
    gemm_kernel<true><<<gemm_grid, gemm_block>>>(out1, W1, n, OUT_C);
    alpha_kernel<<<alpha_blocks, 256>>>(a_src1, a_dst1, n);
    init_kernel<<<init_blocks, 256>>>((float*)d_out, b1, n);
    edge_expsum_kernel<<<edge_blocks, 512>>>(ei, E, Etot);
    recip_kernel<<<recip_blocks, 256>>>(n);
    edge_agg_kernel<<<agg_blocks, 512>>>(ei, E, Etot, (float*)d_out);

    relu_kernel<<<init_blocks, 256>>>((float*)d_out, total);
}

// round 3
// speedup vs baseline: 1.4418x; 1.2992x over previous
#include <cuda_runtime.h>
#include <cuda_bf16.h>
#include <cstdint>

#define N_NODES_MAX 100000
#define IN_C 300
#define OUT_C 200
#define E_MAX 1600000
#define ETOT_MAX (E_MAX + N_NODES_MAX)
#define NEG_SLOPE 0.2f

#define KP0 320   // layer-1 K padded (300 -> 320, /32)
#define KP1 224   // layer-2 K padded (200 -> 224, /32)
#define NPAD 256  // padded N for GEMM tiles (only cols <200 stored)

// ---------------- scratch (device globals; no allocation allowed) ----------
__device__ float g_h[(size_t)N_NODES_MAX * OUT_C];    // projected features (fp32)
__device__ float g_out[(size_t)N_NODES_MAX * OUT_C];  // layer-1 aggregation
__device__ float g_as[N_NODES_MAX];
__device__ float g_ad[N_NODES_MAX];
__device__ float g_s[N_NODES_MAX];
__device__ float g_e[ETOT_MAX];
__device__ int   g_idx64;
// bf16 split buffers (reused across layers; layer uses its own lda)
__device__ __nv_bfloat16 g_ahi[(size_t)N_NODES_MAX * KP0];
__device__ __nv_bfloat16 g_alo[(size_t)N_NODES_MAX * KP0];
__device__ __nv_bfloat16 g_whi[(size_t)NPAD * KP0];
__device__ __nv_bfloat16 g_wlo[(size_t)NPAD * KP0];

// ---------------- helpers ----------------
__device__ __forceinline__ int edge_at(const void* ei, int is64, long long pos) {
    if (is64) return (int)((const long long*)ei)[pos];
    return ((const int*)ei)[pos];
}

__device__ __forceinline__ uint32_t smem_u32(const void* p) {
    return (uint32_t)__cvta_generic_to_shared(p);
}

#define LDSM_X4(r0, r1, r2, r3, addr)                                        \
    asm volatile("ldmatrix.sync.aligned.m8n8.x4.shared.b16 {%0,%1,%2,%3}, [%4];" \
                 : "=r"(r0), "=r"(r1), "=r"(r2), "=r"(r3) : "r"(addr))

#define MMA_BF16(d, a, b)                                                    \
    asm volatile("mma.sync.aligned.m16n8k16.row.col.f32.bf16.bf16.f32 "      \
                 "{%0,%1,%2,%3},{%4,%5,%6,%7},{%8,%9},{%0,%1,%2,%3};"        \
                 : "+f"(d[0]), "+f"(d[1]), "+f"(d[2]), "+f"(d[3])            \
                 : "r"(a[0]), "r"(a[1]), "r"(a[2]), "r"(a[3]),               \
                   "r"(b[0]), "r"(b[1]))

__device__ __forceinline__ void bf16_split(float v, __nv_bfloat16& hi, __nv_bfloat16& lo) {
    hi = __float2bfloat16(v);
    lo = __float2bfloat16(v - __bfloat162float(hi));
}

// Probe edge_index dtype (int64 small values have zero high words).
__global__ void probe_kernel(const int* ei) {
    if (threadIdx.x == 0 && blockIdx.x == 0) {
        int is64 = 1;
        #pragma unroll
        for (int i = 1; i < 32; i += 2)
            if (ei[i] != 0) { is64 = 0; break; }
        g_idx64 = is64;
    }
}

// ---------------- split A: fp32 [rows,K] -> bf16 hi/lo [rows,KP] -----------
template<bool RELU>
__global__ void split_a_kernel(const float* __restrict__ src, int rows, int K, int KP) {
    size_t idx = (size_t)blockIdx.x * blockDim.x + threadIdx.x;
    size_t total = (size_t)rows * KP;
    if (idx >= total) return;
    int k = (int)(idx % KP);
    int r = (int)(idx / KP);
    float v = 0.f;
    if (k < K) v = src[(size_t)r * K + k];
    if (RELU) v = fmaxf(v, 0.f);
    __nv_bfloat16 hi, lo;
    bf16_split(v, hi, lo);
    g_ahi[idx] = hi;
    g_alo[idx] = lo;
}

// ---------------- split W (transposed): W[K,200] -> Wt hi/lo [NPAD,KP] -----
__global__ void split_w_kernel(const float* __restrict__ W, int K, int KP) {
    int idx = blockIdx.x * blockDim.x + threadIdx.x;
    if (idx >= NPAD * KP) return;
    int k = idx % KP;
    int n = idx / KP;
    float v = (k < K && n < OUT_C) ? W[(size_t)k * OUT_C + n] : 0.f;
    __nv_bfloat16 hi, lo;
    bf16_split(v, hi, lo);
    g_whi[idx] = hi;
    g_wlo[idx] = lo;
}

// ---------------- tensor-core GEMM: g_h[M,200] = A @ W -----------------------
// 3-term bf16 split: Ahi*Bhi + Ahi*Blo + Alo*Bhi. BM=128, BN=128, BK=32.
// 8 warps (2m x 4n), warp tile m64 x n32, mma m16n8k16.
__global__ __launch_bounds__(256)
void gemm_tc_kernel(int M, int lda, int kblocks) {
    const int SKP = 40;  // smem k pitch (halves), padded vs 32 for ldmatrix banks
    __shared__ __nv_bfloat16 sAh[128 * SKP];
    __shared__ __nv_bfloat16 sAl[128 * SKP];
    __shared__ __nv_bfloat16 sBh[128 * SKP];
    __shared__ __nv_bfloat16 sBl[128 * SKP];

    int tid = threadIdx.x;
    int lane = tid & 31, warp = tid >> 5;
    int wm = warp & 1, wn = warp >> 1;       // 2 x 4 warp grid
    int bm = blockIdx.x * 128;
    int n0 = blockIdx.y * 128;

    float acc[4][4][4];
    #pragma unroll
    for (int i = 0; i < 4; i++)
        #pragma unroll
        for (int j = 0; j < 4; j++)
            #pragma unroll
            for (int q = 0; q < 4; q++) acc[i][j][q] = 0.f;

    // ldmatrix per-lane row/col within a tile
    int a_r = lane & 15, a_c = (lane >> 4) << 3;          // A: x4 over m16xk16
    int b_r = (lane & 7) + ((lane >> 4) << 3);            // B: x4 over n16xk16
    int b_c = ((lane >> 3) & 1) << 3;

    for (int kb = 0; kb < kblocks; kb++) {
        // load A tiles (128 x 32 halves = 512 uint4), guarded by M
        #pragma unroll
        for (int i = 0; i < 2; i++) {
            int idx = tid + i * 256;
            int row = idx >> 2, q = idx & 3;
            uint4 vh = make_uint4(0, 0, 0, 0), vl = vh;
            if (bm + row < M) {
                size_t off = (size_t)(bm + row) * lda + kb * 32 + q * 8;
                vh = *(const uint4*)(g_ahi + off);
                vl = *(const uint4*)(g_alo + off);
            }
            *(uint4*)(sAh + row * SKP + q * 8) = vh;
            *(uint4*)(sAl + row * SKP + q * 8) = vl;
        }
        // load B tiles (rows n0..n0+127 of Wt, always valid)
        #pragma unroll
        for (int i = 0; i < 2; i++) {
            int idx = tid + i * 256;
            int row = idx >> 2, q = idx & 3;
            size_t off = (size_t)(n0 + row) * lda + kb * 32 + q * 8;
            *(uint4*)(sBh + row * SKP + q * 8) = *(const uint4*)(g_whi + off);
            *(uint4*)(sBl + row * SKP + q * 8) = *(const uint4*)(g_wlo + off);
        }
        __syncthreads();

        #pragma unroll
        for (int ks = 0; ks < 2; ks++) {
            int kh = ks * 16;
            uint32_t ah[4][4], al[4][4], bh[4][2], bl[4][2];
            #pragma unroll
            for (int mi = 0; mi < 4; mi++) {
                int row = wm * 64 + mi * 16 + a_r;
                uint32_t ad = smem_u32(sAh + row * SKP + kh + a_c);
                LDSM_X4(ah[mi][0], ah[mi][1], ah[mi][2], ah[mi][3], ad);
                ad = smem_u32(sAl + row * SKP + kh + a_c);
                LDSM_X4(al[mi][0], al[mi][1], al[mi][2], al[mi][3], ad);
            }
            #pragma unroll
            for (int nj = 0; nj < 2; nj++) {
                int row = wn * 32 + nj * 16 + b_r;
                uint32_t ad = smem_u32(sBh + row * SKP + kh + b_c);
                LDSM_X4(bh[2 * nj][0], bh[2 * nj][1], bh[2 * nj + 1][0], bh[2 * nj + 1][1], ad);
                ad = smem_u32(sBl + row * SKP + kh + b_c);
                LDSM_X4(bl[2 * nj][0], bl[2 * nj][1], bl[2 * nj + 1][0], bl[2 * nj + 1][1], ad);
            }
            #pragma unroll
            for (int mi = 0; mi < 4; mi++)
                #pragma unroll
                for (int ni = 0; ni < 4; ni++) {
                    MMA_BF16(acc[mi][ni], ah[mi], bh[ni]);
                    MMA_BF16(acc[mi][ni], ah[mi], bl[ni]);
                    MMA_BF16(acc[mi][ni], al[mi], bh[ni]);
                }
        }
        __syncthreads();
    }

    // epilogue: store compact pitch-200 fp32
    #pragma unroll
    for (int mi = 0; mi < 4; mi++) {
        int r = bm + wm * 64 + mi * 16 + (lane >> 2);
        #pragma unroll
        for (int ni = 0; ni < 4; ni++) {
            int c = n0 + wn * 32 + ni * 8 + ((lane & 3) << 1);
            if (c >= OUT_C) continue;
            if (r < M)
                *(float2*)(g_h + (size_t)r * OUT_C + c) =
                    make_float2(acc[mi][ni][0], acc[mi][ni][1]);
            if (r + 8 < M)
                *(float2*)(g_h + (size_t)(r + 8) * OUT_C + c) =
                    make_float2(acc[mi][ni][2], acc[mi][ni][3]);
        }
    }
}

// ---------------- alpha_src / alpha_dst: one warp per node ----------------
__global__ void alpha_kernel(const float* __restrict__ a_src,
                             const float* __restrict__ a_dst, int n) {
    int warp = (int)((blockIdx.x * (size_t)blockDim.x + threadIdx.x) >> 5);
    int lane = threadIdx.x & 31;
    if (warp >= n) return;
    const float4* hr  = (const float4*)(g_h + (size_t)warp * OUT_C);
    const float4* as4 = (const float4*)a_src;
    const float4* ad4 = (const float4*)a_dst;
    float s = 0.f, d = 0.f;
    for (int c = lane; c < OUT_C / 4; c += 32) {
        float4 hv = hr[c], av = as4[c], dv = ad4[c];
        s += hv.x * av.x + hv.y * av.y + hv.z * av.z + hv.w * av.w;
        d += hv.x * dv.x + hv.y * dv.y + hv.z * dv.z + hv.w * dv.w;
    }
    #pragma unroll
    for (int o = 16; o; o >>= 1) {
        s += __shfl_down_sync(0xffffffffu, s, o);
        d += __shfl_down_sync(0xffffffffu, d, o);
    }
    if (lane == 0) { g_as[warp] = s; g_ad[warp] = d; }
}

// ---------------- init: out = bias broadcast (float4), s = 0 ---------------
__global__ void init_kernel(float4* __restrict__ out,
                            const float4* __restrict__ b4, int n) {
    int i = blockIdx.x * blockDim.x + threadIdx.x;
    int total4 = n * (OUT_C / 4);
    if (i < total4) out[i] = b4[i % (OUT_C / 4)];
    if (i < n) g_s[i] = 0.f;
}

// ---------------- fused edge pass: ex = exp(leakyrelu(e)), segment sum -----
__global__ void edge_expsum_kernel(const void* __restrict__ ei, int E, int Etot) {
    int i = blockIdx.x * blockDim.x + threadIdx.x;
    if (i >= Etot) return;
    int is64 = g_idx64;
    int src, dst;
    if (i < E) {
        src = edge_at(ei, is64, i);
        dst = edge_at(ei, is64, (long long)E + i);
    } else {
        src = dst = i - E;
    }
    float e = __ldg(&g_as[src]) + __ldg(&g_ad[dst]);
    e = (e > 0.f) ? e : NEG_SLOPE * e;
    float ex = __expf(e);
    g_e[i] = ex;
    atomicAdd(&g_s[dst], ex);
}

// ---------------- reciprocal ------------------------------------------------
__global__ void recip_kernel(int n) {
    int i = blockIdx.x * blockDim.x + threadIdx.x;
    if (i < n) g_s[i] = __frcp_rn(g_s[i]);
}

// ---------------- edge agg: thread per (edge, float4 chunk) ----------------
__global__ void edge_agg_kernel(const void* __restrict__ ei, int E, int Etot,
                                float* __restrict__ out) {
    int t = blockIdx.x * blockDim.x + threadIdx.x;
    int e = (int)((unsigned)t / 50u);
    int c = (int)((unsigned)t % 50u);
    if (e >= Etot) return;
    int is64 = g_idx64;
    int src, dst;
    if (e < E) {
        src = edge_at(ei, is64, e);
        dst = edge_at(ei, is64, (long long)E + e);
    } else {
        src = dst = e - E;
    }
    float alpha = __ldg(&g_e[e]) * __ldg(&g_s[dst]);
    float4 v = __ldg((const float4*)(g_h + (size_t)src * OUT_C) + c);
    float4* op = (float4*)(out + (size_t)dst * OUT_C) + c;
    asm volatile(
        "red.global.add.v4.f32 [%0], {%1, %2, %3, %4};"
        :: "l"(op),
           "f"(v.x * alpha), "f"(v.y * alpha),
           "f"(v.z * alpha), "f"(v.w * alpha)
        : "memory");
}

// ---------------- final relu (float4, in place) ------------------------------
__global__ void relu_kernel(float4* __restrict__ p, int total4) {
    int i = blockIdx.x * blockDim.x + threadIdx.x;
    if (i < total4) {
        float4 v = p[i];
        v.x = fmaxf(v.x, 0.f); v.y = fmaxf(v.y, 0.f);
        v.z = fmaxf(v.z, 0.f); v.w = fmaxf(v.w, 0.f);
        p[i] = v;
    }
}

// ---------------- launch -----------------------------------------------------
extern "C" void kernel_launch(void* const* d_in, const int* in_sizes, int n_in,
                              void* d_out, int out_size) {
    const float* x      = (const float*)d_in[0];
    const float* W0     = (const float*)d_in[1];
    const float* a_src0 = (const float*)d_in[2];
    const float* a_dst0 = (const float*)d_in[3];
    const float* b0     = (const float*)d_in[4];
    const float* W1     = (const float*)d_in[5];
    const float* a_src1 = (const float*)d_in[6];
    const float* a_dst1 = (const float*)d_in[7];
    const float* b1     = (const float*)d_in[8];
    const void*  ei     = d_in[9];

    int n    = in_sizes[0] / IN_C;   // 100000
    int E    = in_sizes[9] / 2;      // 1600000
    int Etot = E + n;

    float* out1;
    cudaGetSymbolAddress((void**)&out1, g_out);

    int total4 = n * (OUT_C / 4);
    dim3 gemm_grid((n + 127) / 128, 2);
    int init_blocks  = (total4 + 255) / 256;
    int alpha_blocks = (n * 32 + 255) / 256;
    int edge_blocks  = (Etot + 511) / 512;
    int recip_blocks = (n + 255) / 256;
    int agg_blocks   = (int)(((long long)Etot * 50 + 511) / 512);
    size_t splitA0 = (size_t)n * KP0, splitA1 = (size_t)n * KP1;
    int sa0_blocks = (int)((splitA0 + 511) / 512);
    int sa1_blocks = (int)((splitA1 + 511) / 512);
    int sw_blocks  = (NPAD * KP0 + 255) / 256;  // max of the two layers

    // ----- layer 1 (gemm is 4th launch -> ncu capture target) -----
    probe_kernel<<<1, 32>>>((const int*)ei);
    split_a_kernel<false><<<sa0_blocks, 512>>>(x, n, IN_C, KP0);
    split_w_kernel<<<sw_blocks, 256>>>(W0, IN_C, KP0);
    gemm_tc_kernel<<<gemm_grid, 256>>>(n, KP0, KP0 / 32);
    alpha_kernel<<<alpha_blocks, 256>>>(a_src0, a_dst0, n);
    init_kernel<<<init_blocks, 256>>>((float4*)out1, (const float4*)b0, n);
    edge_expsum_kernel<<<edge_blocks, 512>>>(ei, E, Etot);
    recip_kernel<<<recip_blocks, 256>>>(n);
    edge_agg_kernel<<<agg_blocks, 512>>>(ei, E, Etot, out1);

    // ----- layer 2 -----
    split_a_kernel<true><<<sa1_blocks, 512>>>(out1, n, OUT_C, KP1);
    split_w_kernel<<<(NPAD * KP1 + 255) / 256, 256>>>(W1, OUT_C, KP1);
    gemm_tc_kernel<<<gemm_grid, 256>>>(n, KP1, KP1 / 32);
    alpha_kernel<<<alpha_blocks, 256>>>(a_src1, a_dst1, n);
    init_kernel<<<init_blocks, 256>>>((float4*)d_out, (const float4*)b1, n);
    edge_expsum_kernel<<<edge_blocks, 512>>>(ei, E, Etot);
    recip_kernel<<<recip_blocks, 256>>>(n);
    edge_agg_kernel<<<agg_blocks, 512>>>(ei, E, Etot, (float*)d_out);

    relu_kernel<<<init_blocks, 256>>>((float4*)d_out, total4);
}

// round 4
// speedup vs baseline: 2.1799x; 1.5119x over previous
#include <cuda_runtime.h>
#include <cuda_bf16.h>
#include <cstdint>

#define N_NODES_MAX 100000
#define IN_C 300
#define OUT_C 200
#define E_MAX 1600000
#define ETOT_MAX (E_MAX + N_NODES_MAX)
#define NEG_SLOPE 0.2f

#define KP0 320   // layer-1 K padded (300 -> 320, /32)
#define KP1 224   // layer-2 K padded (200 -> 224, /32)
#define NPAD 256  // padded N for GEMM tiles (only cols <200 stored)

// ---------------- scratch (device globals; no allocation allowed) ----------
__device__ float g_h[(size_t)N_NODES_MAX * OUT_C];    // projected features (fp32)
__device__ float g_out[(size_t)N_NODES_MAX * OUT_C];  // layer-1 output
__device__ float g_as[N_NODES_MAX];
__device__ float g_ad[N_NODES_MAX];
__device__ float g_s[N_NODES_MAX];                    // 1/denominator
__device__ int   g_idx64;
// CSR (built once per launch, used by both layers)
__device__ int   g_deg[N_NODES_MAX];
__device__ int   g_off[N_NODES_MAX + 1];
__device__ int   g_cur[N_NODES_MAX];
__device__ int   g_csr_src[ETOT_MAX];
__device__ int   g_csr_dst[ETOT_MAX];
__device__ float g_e_csr[ETOT_MAX];
// bf16 split buffers
__device__ __nv_bfloat16 g_ahi[(size_t)N_NODES_MAX * KP0];
__device__ __nv_bfloat16 g_alo[(size_t)N_NODES_MAX * KP0];
__device__ __nv_bfloat16 g_whi[(size_t)NPAD * KP0];
__device__ __nv_bfloat16 g_wlo[(size_t)NPAD * KP0];

// ---------------- helpers ----------------
__device__ __forceinline__ int edge_at(const void* ei, int is64, long long pos) {
    if (is64) return (int)((const long long*)ei)[pos];
    return ((const int*)ei)[pos];
}

__device__ __forceinline__ uint32_t smem_u32(const void* p) {
    return (uint32_t)__cvta_generic_to_shared(p);
}

#define LDSM_X4(r0, r1, r2, r3, addr)                                        \
    asm volatile("ldmatrix.sync.aligned.m8n8.x4.shared.b16 {%0,%1,%2,%3}, [%4];" \
                 : "=r"(r0), "=r"(r1), "=r"(r2), "=r"(r3) : "r"(addr))

#define MMA_BF16(d, a, b)                                                    \
    asm volatile("mma.sync.aligned.m16n8k16.row.col.f32.bf16.bf16.f32 "      \
                 "{%0,%1,%2,%3},{%4,%5,%6,%7},{%8,%9},{%0,%1,%2,%3};"        \
                 : "+f"(d[0]), "+f"(d[1]), "+f"(d[2]), "+f"(d[3])            \
                 : "r"(a[0]), "r"(a[1]), "r"(a[2]), "r"(a[3]),               \
                   "r"(b[0]), "r"(b[1]))

__device__ __forceinline__ void bf16_split(float v, __nv_bfloat16& hi, __nv_bfloat16& lo) {
    hi = __float2bfloat16(v);
    lo = __float2bfloat16(v - __bfloat162float(hi));
}

// Probe edge_index dtype (int64 small values have zero high words).
__global__ void probe_kernel(const int* ei) {
    if (threadIdx.x == 0 && blockIdx.x == 0) {
        int is64 = 1;
        #pragma unroll
        for (int i = 1; i < 32; i += 2)
            if (ei[i] != 0) { is64 = 0; break; }
        g_idx64 = is64;
    }
}

// ---------------- CSR build --------------------------------------------------
__global__ void zero_deg_kernel(int n) {
    int i = blockIdx.x * blockDim.x + threadIdx.x;
    if (i < n) g_deg[i] = 0;
}

__global__ void hist_kernel(const void* __restrict__ ei, int E, int Etot) {
    int i = blockIdx.x * blockDim.x + threadIdx.x;
    if (i >= Etot) return;
    int is64 = g_idx64;
    int dst = (i < E) ? edge_at(ei, is64, (long long)E + i) : (i - E);
    atomicAdd(&g_deg[dst], 1);
}

// single-block exclusive scan over g_deg -> g_off, g_cur
__global__ __launch_bounds__(1024) void scan_kernel(int n) {
    __shared__ int part[1024];
    int t = threadIdx.x;
    int chunk = (n + 1023) >> 10;
    int lo = t * chunk;
    int hi = lo + chunk; if (hi > n) hi = n;
    int s = 0;
    for (int i = lo; i < hi; i++) s += g_deg[i];
    part[t] = s;
    __syncthreads();
    #pragma unroll
    for (int o = 1; o < 1024; o <<= 1) {
        int v = (t >= o) ? part[t - o] : 0;
        __syncthreads();
        part[t] += v;
        __syncthreads();
    }
    int run = (t == 0) ? 0 : part[t - 1];
    for (int i = lo; i < hi; i++) {
        g_off[i] = run;
        g_cur[i] = run;
        run += g_deg[i];
    }
    if (t == 0) g_off[n] = part[1023];
}

__global__ void fill_kernel(const void* __restrict__ ei, int E, int Etot) {
    int i = blockIdx.x * blockDim.x + threadIdx.x;
    if (i >= Etot) return;
    int is64 = g_idx64;
    int src, dst;
    if (i < E) {
        src = edge_at(ei, is64, i);
        dst = edge_at(ei, is64, (long long)E + i);
    } else {
        src = dst = i - E;
    }
    int pos = atomicAdd(&g_cur[dst], 1);
    g_csr_src[pos] = src;
    g_csr_dst[pos] = dst;
}

// ---------------- split A: fp32 [rows,K] -> bf16 hi/lo [rows,KP] -----------
template<bool RELU>
__global__ void split_a_kernel(const float* __restrict__ src, int rows, int K, int KP) {
    size_t idx = (size_t)blockIdx.x * blockDim.x + threadIdx.x;
    size_t total = (size_t)rows * KP;
    if (idx >= total) return;
    int k = (int)(idx % KP);
    int r = (int)(idx / KP);
    float v = 0.f;
    if (k < K) v = src[(size_t)r * K + k];
    if (RELU) v = fmaxf(v, 0.f);
    __nv_bfloat16 hi, lo;
    bf16_split(v, hi, lo);
    g_ahi[idx] = hi;
    g_alo[idx] = lo;
}

// ---------------- split W (transposed): W[K,200] -> Wt hi/lo [NPAD,KP] -----
__global__ void split_w_kernel(const float* __restrict__ W, int K, int KP) {
    int idx = blockIdx.x * blockDim.x + threadIdx.x;
    if (idx >= NPAD * KP) return;
    int k = idx % KP;
    int n = idx / KP;
    float v = (k < K && n < OUT_C) ? W[(size_t)k * OUT_C + n] : 0.f;
    __nv_bfloat16 hi, lo;
    bf16_split(v, hi, lo);
    g_whi[idx] = hi;
    g_wlo[idx] = lo;
}

// ---------------- tensor-core GEMM: g_h[M,200] = A @ W -----------------------
// 3-term bf16 split: Ahi*Bhi + Ahi*Blo + Alo*Bhi. BM=128, BN=128, BK=32.
__global__ __launch_bounds__(256)
void gemm_tc_kernel(int M, int lda, int kblocks) {
    const int SKP = 40;
    __shared__ __nv_bfloat16 sAh[128 * SKP];
    __shared__ __nv_bfloat16 sAl[128 * SKP];
    __shared__ __nv_bfloat16 sBh[128 * SKP];
    __shared__ __nv_bfloat16 sBl[128 * SKP];

    int tid = threadIdx.x;
    int lane = tid & 31, warp = tid >> 5;
    int wm = warp & 1, wn = warp >> 1;
    int bm = blockIdx.x * 128;
    int n0 = blockIdx.y * 128;

    float acc[4][4][4];
    #pragma unroll
    for (int i = 0; i < 4; i++)
        #pragma unroll
        for (int j = 0; j < 4; j++)
            #pragma unroll
            for (int q = 0; q < 4; q++) acc[i][j][q] = 0.f;

    int a_r = lane & 15, a_c = (lane >> 4) << 3;
    int b_r = (lane & 7) + ((lane >> 4) << 3);
    int b_c = ((lane >> 3) & 1) << 3;

    for (int kb = 0; kb < kblocks; kb++) {
        #pragma unroll
        for (int i = 0; i < 2; i++) {
            int idx = tid + i * 256;
            int row = idx >> 2, q = idx & 3;
            uint4 vh = make_uint4(0, 0, 0, 0), vl = vh;
            if (bm + row < M) {
                size_t off = (size_t)(bm + row) * lda + kb * 32 + q * 8;
                vh = *(const uint4*)(g_ahi + off);
                vl = *(const uint4*)(g_alo + off);
            }
            *(uint4*)(sAh + row * SKP + q * 8) = vh;
            *(uint4*)(sAl + row * SKP + q * 8) = vl;
        }
        #pragma unroll
        for (int i = 0; i < 2; i++) {
            int idx = tid + i * 256;
            int row = idx >> 2, q = idx & 3;
            size_t off = (size_t)(n0 + row) * lda + kb * 32 + q * 8;
            *(uint4*)(sBh + row * SKP + q * 8) = *(const uint4*)(g_whi + off);
            *(uint4*)(sBl + row * SKP + q * 8) = *(const uint4*)(g_wlo + off);
        }
        __syncthreads();

        #pragma unroll
        for (int ks = 0; ks < 2; ks++) {
            int kh = ks * 16;
            uint32_t ah[4][4], al[4][4], bh[4][2], bl[4][2];
            #pragma unroll
            for (int mi = 0; mi < 4; mi++) {
                int row = wm * 64 + mi * 16 + a_r;
                uint32_t ad = smem_u32(sAh + row * SKP + kh + a_c);
                LDSM_X4(ah[mi][0], ah[mi][1], ah[mi][2], ah[mi][3], ad);
                ad = smem_u32(sAl + row * SKP + kh + a_c);
                LDSM_X4(al[mi][0], al[mi][1], al[mi][2], al[mi][3], ad);
            }
            #pragma unroll
            for (int nj = 0; nj < 2; nj++) {
                int row = wn * 32 + nj * 16 + b_r;
                uint32_t ad = smem_u32(sBh + row * SKP + kh + b_c);
                LDSM_X4(bh[2 * nj][0], bh[2 * nj][1], bh[2 * nj + 1][0], bh[2 * nj + 1][1], ad);
                ad = smem_u32(sBl + row * SKP + kh + b_c);
                LDSM_X4(bl[2 * nj][0], bl[2 * nj][1], bl[2 * nj + 1][0], bl[2 * nj + 1][1], ad);
            }
            #pragma unroll
            for (int mi = 0; mi < 4; mi++)
                #pragma unroll
                for (int ni = 0; ni < 4; ni++) {
                    MMA_BF16(acc[mi][ni], ah[mi], bh[ni]);
                    MMA_BF16(acc[mi][ni], ah[mi], bl[ni]);
                    MMA_BF16(acc[mi][ni], al[mi], bh[ni]);
                }
        }
        __syncthreads();
    }

    #pragma unroll
    for (int mi = 0; mi < 4; mi++) {
        int r = bm + wm * 64 + mi * 16 + (lane >> 2);
        #pragma unroll
        for (int ni = 0; ni < 4; ni++) {
            int c = n0 + wn * 32 + ni * 8 + ((lane & 3) << 1);
            if (c >= OUT_C) continue;
            if (r < M)
                *(float2*)(g_h + (size_t)r * OUT_C + c) =
                    make_float2(acc[mi][ni][0], acc[mi][ni][1]);
            if (r + 8 < M)
                *(float2*)(g_h + (size_t)(r + 8) * OUT_C + c) =
                    make_float2(acc[mi][ni][2], acc[mi][ni][3]);
        }
    }
}

// ---------------- alpha_src / alpha_dst: one warp per node ----------------
__global__ void alpha_kernel(const float* __restrict__ a_src,
                             const float* __restrict__ a_dst, int n) {
    int warp = (int)((blockIdx.x * (size_t)blockDim.x + threadIdx.x) >> 5);
    int lane = threadIdx.x & 31;
    if (warp >= n) return;
    const float4* hr  = (const float4*)(g_h + (size_t)warp * OUT_C);
    const float4* as4 = (const float4*)a_src;
    const float4* ad4 = (const float4*)a_dst;
    float s = 0.f, d = 0.f;
    for (int c = lane; c < OUT_C / 4; c += 32) {
        float4 hv = hr[c], av = as4[c], dv = ad4[c];
        s += hv.x * av.x + hv.y * av.y + hv.z * av.z + hv.w * av.w;
        d += hv.x * dv.x + hv.y * dv.y + hv.z * dv.z + hv.w * dv.w;
    }
    #pragma unroll
    for (int o = 16; o; o >>= 1) {
        s += __shfl_down_sync(0xffffffffu, s, o);
        d += __shfl_down_sync(0xffffffffu, d, o);
    }
    if (lane == 0) { g_as[warp] = s; g_ad[warp] = d; }
}

// ---------------- passA: per CSR position, ex = exp(leakyrelu(e)) ----------
__global__ void passA_kernel(int Etot) {
    int i = blockIdx.x * blockDim.x + threadIdx.x;
    if (i >= Etot) return;
    int src = g_csr_src[i];
    int dst = g_csr_dst[i];
    float e = __ldg(&g_as[src]) + __ldg(&g_ad[dst]);
    e = (e > 0.f) ? e : NEG_SLOPE * e;
    g_e_csr[i] = __expf(e);
}

// ---------------- passB: warp per dst, g_s = 1 / segment_sum ----------------
__global__ void passB_kernel(int n) {
    int w = (int)((blockIdx.x * (size_t)blockDim.x + threadIdx.x) >> 5);
    int lane = threadIdx.x & 31;
    if (w >= n) return;
    int off = g_off[w], deg = g_deg[w];
    float s = 0.f;
    for (int i = lane; i < deg; i += 32) s += g_e_csr[off + i];
    #pragma unroll
    for (int o = 16; o; o >>= 1) s += __shfl_down_sync(0xffffffffu, s, o);
    if (lane == 0) g_s[w] = __frcp_rn(s);
}

// ---------------- passC: pull aggregation, 64-thread group per dst ----------
// thread (d, c) accumulates chunk c (float4) of out[d] over its CSR row.
template<bool RELU>
__global__ void passC_kernel(int n, float* __restrict__ out,
                             const float* __restrict__ bias) {
    int t = blockIdx.x * blockDim.x + threadIdx.x;
    int d = t >> 6;
    int c = t & 63;
    if (d >= n || c >= OUT_C / 4) return;
    float rs = __ldg(&g_s[d]);
    int off = g_off[d], deg = g_deg[d];
    float4 acc = __ldg((const float4*)bias + c);
    const float4* h4 = (const float4*)g_h;
    for (int j = 0; j < deg; j++) {
        int pos = off + j;
        float a = __ldg(&g_e_csr[pos]) * rs;
        int src = __ldg(&g_csr_src[pos]);
        float4 v = __ldg(h4 + (size_t)src * (OUT_C / 4) + c);
        acc.x = fmaf(a, v.x, acc.x);
        acc.y = fmaf(a, v.y, acc.y);
        acc.z = fmaf(a, v.z, acc.z);
        acc.w = fmaf(a, v.w, acc.w);
    }
    if (RELU) {
        acc.x = fmaxf(acc.x, 0.f); acc.y = fmaxf(acc.y, 0.f);
        acc.z = fmaxf(acc.z, 0.f); acc.w = fmaxf(acc.w, 0.f);
    }
    ((float4*)out)[(size_t)d * (OUT_C / 4) + c] = acc;
}

// ---------------- launch -----------------------------------------------------
extern "C" void kernel_launch(void* const* d_in, const int* in_sizes, int n_in,
                              void* d_out, int out_size) {
    const float* x      = (const float*)d_in[0];
    const float* W0     = (const float*)d_in[1];
    const float* a_src0 = (const float*)d_in[2];
    const float* a_dst0 = (const float*)d_in[3];
    const float* b0     = (const float*)d_in[4];
    const float* W1     = (const float*)d_in[5];
    const float* a_src1 = (const float*)d_in[6];
    const float* a_dst1 = (const float*)d_in[7];
    const float* b1     = (const float*)d_in[8];
    const void*  ei     = d_in[9];

    int n    = in_sizes[0] / IN_C;   // 100000
    int E    = in_sizes[9] / 2;      // 1600000
    int Etot = E + n;

    float* out1;
    cudaGetSymbolAddress((void**)&out1, g_out);

    dim3 gemm_grid((n + 127) / 128, 2);
    int node_blocks  = (n + 255) / 256;
    int alpha_blocks = (n * 32 + 255) / 256;
    int edge_blocks  = (Etot + 511) / 512;
    int warp_blocks  = (int)(((long long)n * 32 + 255) / 256);
    int aggC_blocks  = (int)(((long long)n * 64 + 255) / 256);
    size_t splitA0 = (size_t)n * KP0, splitA1 = (size_t)n * KP1;
    int sa0_blocks = (int)((splitA0 + 511) / 512);
    int sa1_blocks = (int)((splitA1 + 511) / 512);

    // ----- CSR build (once, shared by both layers) -----
    probe_kernel<<<1, 32>>>((const int*)ei);
    zero_deg_kernel<<<node_blocks, 256>>>(n);
    hist_kernel<<<edge_blocks, 512>>>(ei, E, Etot);
    scan_kernel<<<1, 1024>>>(n);
    fill_kernel<<<edge_blocks, 512>>>(ei, E, Etot);

    // ----- layer 1 -----
    split_a_kernel<false><<<sa0_blocks, 512>>>(x, n, IN_C, KP0);
    split_w_kernel<<<(NPAD * KP0 + 255) / 256, 256>>>(W0, IN_C, KP0);
    gemm_tc_kernel<<<gemm_grid, 256>>>(n, KP0, KP0 / 32);
    alpha_kernel<<<alpha_blocks, 256>>>(a_src0, a_dst0, n);
    passA_kernel<<<edge_blocks, 512>>>(Etot);
    passB_kernel<<<warp_blocks, 256>>>(n);
    passC_kernel<false><<<aggC_blocks, 256>>>(n, out1, b0);

    // ----- layer 2 -----
    split_a_kernel<true><<<sa1_blocks, 512>>>(out1, n, OUT_C, KP1);
    split_w_kernel<<<(NPAD * KP1 + 255) / 256, 256>>>(W1, OUT_C, KP1);
    gemm_tc_kernel<<<gemm_grid, 256>>>(n, KP1, KP1 / 32);
    alpha_kernel<<<alpha_blocks, 256>>>(a_src1, a_dst1, n);
    passA_kernel<<<edge_blocks, 512>>>(Etot);
    passB_kernel<<<warp_blocks, 256>>>(n);
    passC_kernel<true><<<aggC_blocks, 256>>>(n, (float*)d_out, b1);
}

// round 5
// speedup vs baseline: 2.6719x; 1.2257x over previous
#include <cuda_runtime.h>
#include <cuda_bf16.h>
#include <cstdint>

#define N_NODES_MAX 100000
#define IN_C 300
#define OUT_C 200
#define E_MAX 1600000
#define ETOT_MAX (E_MAX + N_NODES_MAX)
#define NEG_SLOPE 0.2f

#define KP0 320
#define KP1 224
#define NPAD 256
#define SKP 40            // smem k pitch (halves)
#define TS (128 * SKP)    // halves per tile array
#define GEMM_SMEM (2 * 4 * TS * 2)  // 2 stages * 4 arrays * TS halves * 2B

// ---------------- scratch ----------------
__device__ float g_h[(size_t)N_NODES_MAX * OUT_C];
__device__ float g_out[(size_t)N_NODES_MAX * OUT_C];
__device__ float g_as[N_NODES_MAX];
__device__ float g_ad[N_NODES_MAX];
__device__ float g_s[N_NODES_MAX];
__device__ int   g_idx64;
// CSR
__device__ int   g_deg[N_NODES_MAX];
__device__ int   g_off[N_NODES_MAX + 1];
__device__ int   g_cur[N_NODES_MAX];
__device__ int   g_bsum[256];
__device__ int   g_boff[257];
__device__ int   g_csr_src[ETOT_MAX];
__device__ int   g_csr_dst[ETOT_MAX];
__device__ float g_e_csr[ETOT_MAX];
// bf16 split buffers
__device__ __nv_bfloat16 g_ahi[(size_t)N_NODES_MAX * KP0];
__device__ __nv_bfloat16 g_alo[(size_t)N_NODES_MAX * KP0];
__device__ __nv_bfloat16 g_whi[(size_t)NPAD * KP0];
__device__ __nv_bfloat16 g_wlo[(size_t)NPAD * KP0];

// ---------------- helpers ----------------
__device__ __forceinline__ int edge_at(const void* ei, int is64, long long pos) {
    if (is64) return (int)((const long long*)ei)[pos];
    return ((const int*)ei)[pos];
}

__device__ __forceinline__ uint32_t smem_u32(const void* p) {
    return (uint32_t)__cvta_generic_to_shared(p);
}

__device__ __forceinline__ void cp16(uint32_t dst, const void* src, bool pred) {
    int sz = pred ? 16 : 0;
    asm volatile("cp.async.cg.shared.global [%0], [%1], 16, %2;"
                 :: "r"(dst), "l"(src), "r"(sz));
}

#define CP_COMMIT() asm volatile("cp.async.commit_group;")
#define CP_WAIT(N)  asm volatile("cp.async.wait_group %0;" :: "n"(N))

#define LDSM_X4(r0, r1, r2, r3, addr)                                        \
    asm volatile("ldmatrix.sync.aligned.m8n8.x4.shared.b16 {%0,%1,%2,%3}, [%4];" \
                 : "=r"(r0), "=r"(r1), "=r"(r2), "=r"(r3) : "r"(addr))

#define MMA_BF16(d, a, b)                                                    \
    asm volatile("mma.sync.aligned.m16n8k16.row.col.f32.bf16.bf16.f32 "      \
                 "{%0,%1,%2,%3},{%4,%5,%6,%7},{%8,%9},{%0,%1,%2,%3};"        \
                 : "+f"(d[0]), "+f"(d[1]), "+f"(d[2]), "+f"(d[3])            \
                 : "r"(a[0]), "r"(a[1]), "r"(a[2]), "r"(a[3]),               \
                   "r"(b[0]), "r"(b[1]))

__device__ __forceinline__ void bf16_split(float v, __nv_bfloat16& hi, __nv_bfloat16& lo) {
    hi = __float2bfloat16(v);
    lo = __float2bfloat16(v - __bfloat162float(hi));
}

__global__ void probe_kernel(const int* ei) {
    if (threadIdx.x == 0 && blockIdx.x == 0) {
        int is64 = 1;
        #pragma unroll
        for (int i = 1; i < 32; i += 2)
            if (ei[i] != 0) { is64 = 0; break; }
        g_idx64 = is64;
    }
}

// ---------------- CSR build --------------------------------------------------
__global__ void zero_deg_kernel(int n) {
    int i = blockIdx.x * blockDim.x + threadIdx.x;
    if (i < n) g_deg[i] = 0;
}

__global__ void hist_kernel(const void* __restrict__ ei, int E, int Etot) {
    int i = blockIdx.x * blockDim.x + threadIdx.x;
    if (i >= Etot) return;
    int is64 = g_idx64;
    int dst = (i < E) ? edge_at(ei, is64, (long long)E + i) : (i - E);
    atomicAdd(&g_deg[dst], 1);
}

// two-level scan: scan1 per-block, scan2 block sums, scan3 add offsets
__global__ __launch_bounds__(1024) void scan1_kernel(int n) {
    __shared__ int sh[1024];
    int t = threadIdx.x;
    int i = blockIdx.x * 1024 + t;
    int v = (i < n) ? g_deg[i] : 0;
    sh[t] = v;
    __syncthreads();
    #pragma unroll
    for (int o = 1; o < 1024; o <<= 1) {
        int u = (t >= o) ? sh[t - o] : 0;
        __syncthreads();
        sh[t] += u;
        __syncthreads();
    }
    if (i < n) g_off[i] = sh[t] - v;           // block-local exclusive
    if (t == 1023) g_bsum[blockIdx.x] = sh[1023];
}

__global__ __launch_bounds__(128) void scan2_kernel(int nb) {
    __shared__ int sh[128];
    int t = threadIdx.x;
    int v = (t < nb) ? g_bsum[t] : 0;
    sh[t] = v;
    __syncthreads();
    #pragma unroll
    for (int o = 1; o < 128; o <<= 1) {
        int u = (t >= o) ? sh[t - o] : 0;
        __syncthreads();
        sh[t] += u;
        __syncthreads();
    }
    g_boff[t] = sh[t] - v;                     // exclusive
    if (t == 127) g_boff[128] = sh[127];       // grand total (nb<=128)
}

__global__ void scan3_kernel(int n) {
    int i = blockIdx.x * blockDim.x + threadIdx.x;
    if (i < n) {
        int o = g_off[i] + g_boff[i >> 10];
        g_off[i] = o;
        g_cur[i] = o;
    }
    if (i == 0) g_off[n] = g_boff[128];
}

__global__ void fill_kernel(const void* __restrict__ ei, int E, int Etot) {
    int i = blockIdx.x * blockDim.x + threadIdx.x;
    if (i >= Etot) return;
    int is64 = g_idx64;
    int src, dst;
    if (i < E) {
        src = edge_at(ei, is64, i);
        dst = edge_at(ei, is64, (long long)E + i);
    } else {
        src = dst = i - E;
    }
    int pos = atomicAdd(&g_cur[dst], 1);
    g_csr_src[pos] = src;
    g_csr_dst[pos] = dst;
}

// ---------------- splits -----------------------------------------------------
template<bool RELU>
__global__ void split_a_kernel(const float* __restrict__ src, int rows, int K, int KP) {
    size_t idx = (size_t)blockIdx.x * blockDim.x + threadIdx.x;
    size_t total = (size_t)rows * KP;
    if (idx >= total) return;
    int k = (int)(idx % KP);
    int r = (int)(idx / KP);
    float v = 0.f;
    if (k < K) v = src[(size_t)r * K + k];
    if (RELU) v = fmaxf(v, 0.f);
    __nv_bfloat16 hi, lo;
    bf16_split(v, hi, lo);
    g_ahi[idx] = hi;
    g_alo[idx] = lo;
}

__global__ void split_w_kernel(const float* __restrict__ W, int K, int KP) {
    int idx = blockIdx.x * blockDim.x + threadIdx.x;
    if (idx >= NPAD * KP) return;
    int k = idx % KP;
    int n = idx / KP;
    float v = (k < K && n < OUT_C) ? W[(size_t)k * OUT_C + n] : 0.f;
    __nv_bfloat16 hi, lo;
    bf16_split(v, hi, lo);
    g_whi[idx] = hi;
    g_wlo[idx] = lo;
}

// ---------------- tensor-core GEMM (2-stage cp.async pipeline) --------------
__global__ __launch_bounds__(256)
void gemm_tc_kernel(int M, int lda, int kblocks) {
    extern __shared__ __nv_bfloat16 smem[];

    int tid = threadIdx.x;
    int lane = tid & 31, warp = tid >> 5;
    int wm = warp & 1, wn = warp >> 1;
    int bm = blockIdx.x * 128;
    int n0 = blockIdx.y * 128;

    float acc[4][4][4];
    #pragma unroll
    for (int i = 0; i < 4; i++)
        #pragma unroll
        for (int j = 0; j < 4; j++)
            #pragma unroll
            for (int q = 0; q < 4; q++) acc[i][j][q] = 0.f;

    int a_r = lane & 15, a_c = (lane >> 4) << 3;
    int b_r = (lane & 7) + ((lane >> 4) << 3);
    int b_c = ((lane >> 3) & 1) << 3;

    // stage loader
    auto load_stage = [&](int kb, int s) {
        __nv_bfloat16* sAh = smem + s * 4 * TS;
        __nv_bfloat16* sAl = sAh + TS;
        __nv_bfloat16* sBh = sAl + TS;
        __nv_bfloat16* sBl = sBh + TS;
        #pragma unroll
        for (int i = 0; i < 2; i++) {
            int idx = tid + i * 256;
            int row = idx >> 2, q = idx & 3;
            bool vA = (bm + row) < M;
            int rA = vA ? (bm + row) : 0;
            size_t offA = (size_t)rA * lda + kb * 32 + q * 8;
            cp16(smem_u32(sAh + row * SKP + q * 8), g_ahi + offA, vA);
            cp16(smem_u32(sAl + row * SKP + q * 8), g_alo + offA, vA);
            size_t offB = (size_t)(n0 + row) * lda + kb * 32 + q * 8;
            cp16(smem_u32(sBh + row * SKP + q * 8), g_whi + offB, true);
            cp16(smem_u32(sBl + row * SKP + q * 8), g_wlo + offB, true);
        }
        CP_COMMIT();
    };

    load_stage(0, 0);

    for (int kb = 0; kb < kblocks; kb++) {
        if (kb + 1 < kblocks) {
            load_stage(kb + 1, (kb + 1) & 1);
            CP_WAIT(1);
        } else {
            CP_WAIT(0);
        }
        __syncthreads();

        int s = kb & 1;
        __nv_bfloat16* sAh = smem + s * 4 * TS;
        __nv_bfloat16* sAl = sAh + TS;
        __nv_bfloat16* sBh = sAl + TS;
        __nv_bfloat16* sBl = sBh + TS;

        #pragma unroll
        for (int ks = 0; ks < 2; ks++) {
            int kh = ks * 16;
            uint32_t ah[4][4], al[4][4], bh[4][2], bl[4][2];
            #pragma unroll
            for (int mi = 0; mi < 4; mi++) {
                int row = wm * 64 + mi * 16 + a_r;
                uint32_t ad = smem_u32(sAh + row * SKP + kh + a_c);
                LDSM_X4(ah[mi][0], ah[mi][1], ah[mi][2], ah[mi][3], ad);
                ad = smem_u32(sAl + row * SKP + kh + a_c);
                LDSM_X4(al[mi][0], al[mi][1], al[mi][2], al[mi][3], ad);
            }
            #pragma unroll
            for (int nj = 0; nj < 2; nj++) {
                int row = wn * 32 + nj * 16 + b_r;
                uint32_t ad = smem_u32(sBh + row * SKP + kh + b_c);
                LDSM_X4(bh[2 * nj][0], bh[2 * nj][1], bh[2 * nj + 1][0], bh[2 * nj + 1][1], ad);
                ad = smem_u32(sBl + row * SKP + kh + b_c);
                LDSM_X4(bl[2 * nj][0], bl[2 * nj][1], bl[2 * nj + 1][0], bl[2 * nj + 1][1], ad);
            }
            #pragma unroll
            for (int mi = 0; mi < 4; mi++)
                #pragma unroll
                for (int ni = 0; ni < 4; ni++) {
                    MMA_BF16(acc[mi][ni], ah[mi], bh[ni]);
                    MMA_BF16(acc[mi][ni], ah[mi], bl[ni]);
                    MMA_BF16(acc[mi][ni], al[mi], bh[ni]);
                }
        }
        __syncthreads();
    }

    #pragma unroll
    for (int mi = 0; mi < 4; mi++) {
        int r = bm + wm * 64 + mi * 16 + (lane >> 2);
        #pragma unroll
        for (int ni = 0; ni < 4; ni++) {
            int c = n0 + wn * 32 + ni * 8 + ((lane & 3) << 1);
            if (c >= OUT_C) continue;
            if (r < M)
                *(float2*)(g_h + (size_t)r * OUT_C + c) =
                    make_float2(acc[mi][ni][0], acc[mi][ni][1]);
            if (r + 8 < M)
                *(float2*)(g_h + (size_t)(r + 8) * OUT_C + c) =
                    make_float2(acc[mi][ni][2], acc[mi][ni][3]);
        }
    }
}

// ---------------- alpha ------------------------------------------------------
__global__ void alpha_kernel(const float* __restrict__ a_src,
                             const float* __restrict__ a_dst, int n) {
    int warp = (int)((blockIdx.x * (size_t)blockDim.x + threadIdx.x) >> 5);
    int lane = threadIdx.x & 31;
    if (warp >= n) return;
    const float4* hr  = (const float4*)(g_h + (size_t)warp * OUT_C);
    const float4* as4 = (const float4*)a_src;
    const float4* ad4 = (const float4*)a_dst;
    float s = 0.f, d = 0.f;
    for (int c = lane; c < OUT_C / 4; c += 32) {
        float4 hv = hr[c], av = as4[c], dv = ad4[c];
        s += hv.x * av.x + hv.y * av.y + hv.z * av.z + hv.w * av.w;
        d += hv.x * dv.x + hv.y * dv.y + hv.z * dv.z + hv.w * dv.w;
    }
    #pragma unroll
    for (int o = 16; o; o >>= 1) {
        s += __shfl_down_sync(0xffffffffu, s, o);
        d += __shfl_down_sync(0xffffffffu, d, o);
    }
    if (lane == 0) { g_as[warp] = s; g_ad[warp] = d; }
}

// ---------------- passA / passB / passC --------------------------------------
__global__ void passA_kernel(int Etot) {
    int i = blockIdx.x * blockDim.x + threadIdx.x;
    if (i >= Etot) return;
    int src = g_csr_src[i];
    int dst = g_csr_dst[i];
    float e = __ldg(&g_as[src]) + __ldg(&g_ad[dst]);
    e = (e > 0.f) ? e : NEG_SLOPE * e;
    g_e_csr[i] = __expf(e);
}

__global__ void passB_kernel(int n) {
    int w = (int)((blockIdx.x * (size_t)blockDim.x + threadIdx.x) >> 5);
    int lane = threadIdx.x & 31;
    if (w >= n) return;
    int off = g_off[w], deg = g_deg[w];
    float s = 0.f;
    for (int i = lane; i < deg; i += 32) s += g_e_csr[off + i];
    #pragma unroll
    for (int o = 16; o; o >>= 1) s += __shfl_down_sync(0xffffffffu, s, o);
    if (lane == 0) g_s[w] = __frcp_rn(s);
}

template<bool RELU>
__global__ void passC_kernel(int n, float* __restrict__ out,
                             const float* __restrict__ bias) {
    int t = blockIdx.x * blockDim.x + threadIdx.x;
    int d = t >> 6;
    int c = t & 63;
    if (d >= n || c >= OUT_C / 4) return;
    float rs = __ldg(&g_s[d]);
    int off = g_off[d], deg = g_deg[d];
    float4 acc = __ldg((const float4*)bias + c);
    const float4* h4 = (const float4*)g_h;
    for (int j = 0; j < deg; j++) {
        int pos = off + j;
        float a = __ldg(&g_e_csr[pos]) * rs;
        int src = __ldg(&g_csr_src[pos]);
        float4 v = __ldg(h4 + (size_t)src * (OUT_C / 4) + c);
        acc.x = fmaf(a, v.x, acc.x);
        acc.y = fmaf(a, v.y, acc.y);
        acc.z = fmaf(a, v.z, acc.z);
        acc.w = fmaf(a, v.w, acc.w);
    }
    if (RELU) {
        acc.x = fmaxf(acc.x, 0.f); acc.y = fmaxf(acc.y, 0.f);
        acc.z = fmaxf(acc.z, 0.f); acc.w = fmaxf(acc.w, 0.f);
    }
    ((float4*)out)[(size_t)d * (OUT_C / 4) + c] = acc;
}

// ---------------- launch -----------------------------------------------------
extern "C" void kernel_launch(void* const* d_in, const int* in_sizes, int n_in,
                              void* d_out, int out_size) {
    const float* x      = (const float*)d_in[0];
    const float* W0     = (const float*)d_in[1];
    const float* a_src0 = (const float*)d_in[2];
    const float* a_dst0 = (const float*)d_in[3];
    const float* b0     = (const float*)d_in[4];
    const float* W1     = (const float*)d_in[5];
    const float* a_src1 = (const float*)d_in[6];
    const float* a_dst1 = (const float*)d_in[7];
    const float* b1     = (const float*)d_in[8];
    const void*  ei     = d_in[9];

    int n    = in_sizes[0] / IN_C;   // 100000
    int E    = in_sizes[9] / 2;      // 1600000
    int Etot = E + n;

    float* out1;
    cudaGetSymbolAddress((void**)&out1, g_out);

    cudaFuncSetAttribute(gemm_tc_kernel,
                         cudaFuncAttributeMaxDynamicSharedMemorySize, GEMM_SMEM);

    dim3 gemm_grid((n + 127) / 128, 2);
    int node_blocks  = (n + 255) / 256;
    int alpha_blocks = (n * 32 + 255) / 256;
    int edge_blocks  = (Etot + 511) / 512;
    int scan_blocks  = (n + 1023) / 1024;   // 98
    int warp_blocks  = (int)(((long long)n * 32 + 255) / 256);
    int aggC_blocks  = (int)(((long long)n * 64 + 255) / 256);
    size_t splitA0 = (size_t)n * KP0, splitA1 = (size_t)n * KP1;
    int sa0_blocks = (int)((splitA0 + 511) / 512);
    int sa1_blocks = (int)((splitA1 + 511) / 512);

    // ----- CSR build (once) -----
    probe_kernel<<<1, 32>>>((const int*)ei);
    zero_deg_kernel<<<node_blocks, 256>>>(n);
    hist_kernel<<<edge_blocks, 512>>>(ei, E, Etot);
    scan1_kernel<<<scan_blocks, 1024>>>(n);
    scan2_kernel<<<1, 128>>>(scan_blocks);
    scan3_kernel<<<node_blocks, 256>>>(n);
    fill_kernel<<<edge_blocks, 512>>>(ei, E, Etot);

    // ----- layer 1 -----
    split_a_kernel<false><<<sa0_blocks, 512>>>(x, n, IN_C, KP0);
    split_w_kernel<<<(NPAD * KP0 + 255) / 256, 256>>>(W0, IN_C, KP0);
    gemm_tc_kernel<<<gemm_grid, 256, GEMM_SMEM>>>(n, KP0, KP0 / 32);
    alpha_kernel<<<alpha_blocks, 256>>>(a_src0, a_dst0, n);
    passA_kernel<<<edge_blocks, 512>>>(Etot);
    passB_kernel<<<warp_blocks, 256>>>(n);
    passC_kernel<false><<<aggC_blocks, 256>>>(n, out1, b0);

    // ----- layer 2 -----
    split_a_kernel<true><<<sa1_blocks, 512>>>(out1, n, OUT_C, KP1);
    split_w_kernel<<<(NPAD * KP1 + 255) / 256, 256>>>(W1, OUT_C, KP1);
    gemm_tc_kernel<<<gemm_grid, 256, GEMM_SMEM>>>(n, KP1, KP1 / 32);
    alpha_kernel<<<alpha_blocks, 256>>>(a_src1, a_dst1, n);
    passA_kernel<<<edge_blocks, 512>>>(Etot);
    passB_kernel<<<warp_blocks, 256>>>(n);
    passC_kernel<true><<<aggC_blocks, 256>>>(n, (float*)d_out, b1);
}

// round 6
// speedup vs baseline: 2.8036x; 1.0493x over previous
#include <cuda_runtime.h>
#include <cuda_bf16.h>
#include <cstdint>

#define N_NODES_MAX 100000
#define IN_C 300
#define OUT_C 200
#define E_MAX 1600000
#define ETOT_MAX (E_MAX + N_NODES_MAX)
#define NEG_SLOPE 0.2f

#define KP0 320
#define KP1 224
#define NPAD 256
#define SKP 40            // smem k pitch (halves)
#define TS (128 * SKP)    // halves per tile array
#define GEMM_SMEM (2 * 4 * TS * 2)  // 2 stages * 4 arrays * TS halves * 2B

// ---------------- scratch ----------------
__device__ float g_h[(size_t)N_NODES_MAX * OUT_C];
__device__ float g_as[N_NODES_MAX];
__device__ float g_ad[N_NODES_MAX];
__device__ float g_s[N_NODES_MAX];
__device__ int   g_idx64;
// CSR
__device__ int   g_deg[N_NODES_MAX];
__device__ int   g_off[N_NODES_MAX + 1];
__device__ int   g_cur[N_NODES_MAX];
__device__ int   g_bsum[256];
__device__ int   g_boff[257];
__device__ int   g_csr_src[ETOT_MAX];
__device__ int   g_csr_dst[ETOT_MAX];
__device__ float g_e_csr[ETOT_MAX];
// bf16 split buffers
__device__ __nv_bfloat16 g_ahi[(size_t)N_NODES_MAX * KP0];
__device__ __nv_bfloat16 g_alo[(size_t)N_NODES_MAX * KP0];
__device__ __nv_bfloat16 g_whi[(size_t)NPAD * KP0];
__device__ __nv_bfloat16 g_wlo[(size_t)NPAD * KP0];

// ---------------- helpers ----------------
__device__ __forceinline__ int edge_at(const void* ei, int is64, long long pos) {
    if (is64) return (int)((const long long*)ei)[pos];
    return ((const int*)ei)[pos];
}

__device__ __forceinline__ uint32_t smem_u32(const void* p) {
    return (uint32_t)__cvta_generic_to_shared(p);
}

__device__ __forceinline__ void cp16(uint32_t dst, const void* src, bool pred) {
    int sz = pred ? 16 : 0;
    asm volatile("cp.async.cg.shared.global [%0], [%1], 16, %2;"
                 :: "r"(dst), "l"(src), "r"(sz));
}

#define CP_COMMIT() asm volatile("cp.async.commit_group;")
#define CP_WAIT(N)  asm volatile("cp.async.wait_group %0;" :: "n"(N))

#define LDSM_X4(r0, r1, r2, r3, addr)                                        \
    asm volatile("ldmatrix.sync.aligned.m8n8.x4.shared.b16 {%0,%1,%2,%3}, [%4];" \
                 : "=r"(r0), "=r"(r1), "=r"(r2), "=r"(r3) : "r"(addr))

#define MMA_BF16(d, a, b)                                                    \
    asm volatile("mma.sync.aligned.m16n8k16.row.col.f32.bf16.bf16.f32 "      \
                 "{%0,%1,%2,%3},{%4,%5,%6,%7},{%8,%9},{%0,%1,%2,%3};"        \
                 : "+f"(d[0]), "+f"(d[1]), "+f"(d[2]), "+f"(d[3])            \
                 : "r"(a[0]), "r"(a[1]), "r"(a[2]), "r"(a[3]),               \
                   "r"(b[0]), "r"(b[1]))

__device__ __forceinline__ void bf16_split(float v, __nv_bfloat16& hi, __nv_bfloat16& lo) {
    hi = __float2bfloat16(v);
    lo = __float2bfloat16(v - __bfloat162float(hi));
}

__global__ void probe_kernel(const int* ei) {
    if (threadIdx.x == 0 && blockIdx.x == 0) {
        int is64 = 1;
        #pragma unroll
        for (int i = 1; i < 32; i += 2)
            if (ei[i] != 0) { is64 = 0; break; }
        g_idx64 = is64;
    }
}

// ---------------- zero as/ad (before each gemm, epilogue atomics) ----------
__global__ void zero_asad_kernel(int n) {
    int i = blockIdx.x * blockDim.x + threadIdx.x;
    if (i < n) { g_as[i] = 0.f; g_ad[i] = 0.f; }
}

// ---------------- CSR build --------------------------------------------------
__global__ void zero_deg_kernel(int n) {
    int i = blockIdx.x * blockDim.x + threadIdx.x;
    if (i < n) g_deg[i] = 0;
}

__global__ void hist_kernel(const void* __restrict__ ei, int E, int Etot) {
    int i = blockIdx.x * blockDim.x + threadIdx.x;
    if (i >= Etot) return;
    int is64 = g_idx64;
    int dst = (i < E) ? edge_at(ei, is64, (long long)E + i) : (i - E);
    atomicAdd(&g_deg[dst], 1);
}

__global__ __launch_bounds__(1024) void scan1_kernel(int n) {
    __shared__ int sh[1024];
    int t = threadIdx.x;
    int i = blockIdx.x * 1024 + t;
    int v = (i < n) ? g_deg[i] : 0;
    sh[t] = v;
    __syncthreads();
    #pragma unroll
    for (int o = 1; o < 1024; o <<= 1) {
        int u = (t >= o) ? sh[t - o] : 0;
        __syncthreads();
        sh[t] += u;
        __syncthreads();
    }
    if (i < n) g_off[i] = sh[t] - v;
    if (t == 1023) g_bsum[blockIdx.x] = sh[1023];
}

__global__ __launch_bounds__(128) void scan2_kernel(int nb) {
    __shared__ int sh[128];
    int t = threadIdx.x;
    int v = (t < nb) ? g_bsum[t] : 0;
    sh[t] = v;
    __syncthreads();
    #pragma unroll
    for (int o = 1; o < 128; o <<= 1) {
        int u = (t >= o) ? sh[t - o] : 0;
        __syncthreads();
        sh[t] += u;
        __syncthreads();
    }
    g_boff[t] = sh[t] - v;
    if (t == 127) g_boff[128] = sh[127];
}

__global__ void scan3_kernel(int n) {
    int i = blockIdx.x * blockDim.x + threadIdx.x;
    if (i < n) {
        int o = g_off[i] + g_boff[i >> 10];
        g_off[i] = o;
        g_cur[i] = o;
    }
    if (i == 0) g_off[n] = g_boff[128];
}

__global__ void fill_kernel(const void* __restrict__ ei, int E, int Etot) {
    int i = blockIdx.x * blockDim.x + threadIdx.x;
    if (i >= Etot) return;
    int is64 = g_idx64;
    int src, dst;
    if (i < E) {
        src = edge_at(ei, is64, i);
        dst = edge_at(ei, is64, (long long)E + i);
    } else {
        src = dst = i - E;
    }
    int pos = atomicAdd(&g_cur[dst], 1);
    g_csr_src[pos] = src;
    g_csr_dst[pos] = dst;
}

// ---------------- split A (layer 1 only) -------------------------------------
__global__ void split_a_kernel(const float* __restrict__ src, int rows, int K, int KP) {
    size_t idx = (size_t)blockIdx.x * blockDim.x + threadIdx.x;
    size_t total = (size_t)rows * KP;
    if (idx >= total) return;
    int k = (int)(idx % KP);
    int r = (int)(idx / KP);
    float v = 0.f;
    if (k < K) v = src[(size_t)r * K + k];
    __nv_bfloat16 hi, lo;
    bf16_split(v, hi, lo);
    g_ahi[idx] = hi;
    g_alo[idx] = lo;
}

__global__ void split_w_kernel(const float* __restrict__ W, int K, int KP) {
    int idx = blockIdx.x * blockDim.x + threadIdx.x;
    if (idx >= NPAD * KP) return;
    int k = idx % KP;
    int n = idx / KP;
    float v = (k < K && n < OUT_C) ? W[(size_t)k * OUT_C + n] : 0.f;
    __nv_bfloat16 hi, lo;
    bf16_split(v, hi, lo);
    g_whi[idx] = hi;
    g_wlo[idx] = lo;
}

// ---------------- tensor-core GEMM + fused alpha epilogue --------------------
__global__ __launch_bounds__(256)
void gemm_tc_kernel(int M, int lda, int kblocks,
                    const float* __restrict__ a_src,
                    const float* __restrict__ a_dst) {
    extern __shared__ __nv_bfloat16 smem[];

    int tid = threadIdx.x;
    int lane = tid & 31, warp = tid >> 5;
    int wm = warp & 1, wn = warp >> 1;
    int bm = blockIdx.x * 128;
    int n0 = blockIdx.y * 128;

    float acc[4][4][4];
    #pragma unroll
    for (int i = 0; i < 4; i++)
        #pragma unroll
        for (int j = 0; j < 4; j++)
            #pragma unroll
            for (int q = 0; q < 4; q++) acc[i][j][q] = 0.f;

    int a_r = lane & 15, a_c = (lane >> 4) << 3;
    int b_r = (lane & 7) + ((lane >> 4) << 3);
    int b_c = ((lane >> 3) & 1) << 3;

    auto load_stage = [&](int kb, int s) {
        __nv_bfloat16* sAh = smem + s * 4 * TS;
        __nv_bfloat16* sAl = sAh + TS;
        __nv_bfloat16* sBh = sAl + TS;
        __nv_bfloat16* sBl = sBh + TS;
        #pragma unroll
        for (int i = 0; i < 2; i++) {
            int idx = tid + i * 256;
            int row = idx >> 2, q = idx & 3;
            bool vA = (bm + row) < M;
            int rA = vA ? (bm + row) : 0;
            size_t offA = (size_t)rA * lda + kb * 32 + q * 8;
            cp16(smem_u32(sAh + row * SKP + q * 8), g_ahi + offA, vA);
            cp16(smem_u32(sAl + row * SKP + q * 8), g_alo + offA, vA);
            size_t offB = (size_t)(n0 + row) * lda + kb * 32 + q * 8;
            cp16(smem_u32(sBh + row * SKP + q * 8), g_whi + offB, true);
            cp16(smem_u32(sBl + row * SKP + q * 8), g_wlo + offB, true);
        }
        CP_COMMIT();
    };

    load_stage(0, 0);

    for (int kb = 0; kb < kblocks; kb++) {
        if (kb + 1 < kblocks) {
            load_stage(kb + 1, (kb + 1) & 1);
            CP_WAIT(1);
        } else {
            CP_WAIT(0);
        }
        __syncthreads();

        int s = kb & 1;
        __nv_bfloat16* sAh = smem + s * 4 * TS;
        __nv_bfloat16* sAl = sAh + TS;
        __nv_bfloat16* sBh = sAl + TS;
        __nv_bfloat16* sBl = sBh + TS;

        #pragma unroll
        for (int ks = 0; ks < 2; ks++) {
            int kh = ks * 16;
            uint32_t ah[4][4], al[4][4], bh[4][2], bl[4][2];
            #pragma unroll
            for (int mi = 0; mi < 4; mi++) {
                int row = wm * 64 + mi * 16 + a_r;
                uint32_t ad = smem_u32(sAh + row * SKP + kh + a_c);
                LDSM_X4(ah[mi][0], ah[mi][1], ah[mi][2], ah[mi][3], ad);
                ad = smem_u32(sAl + row * SKP + kh + a_c);
                LDSM_X4(al[mi][0], al[mi][1], al[mi][2], al[mi][3], ad);
            }
            #pragma unroll
            for (int nj = 0; nj < 2; nj++) {
                int row = wn * 32 + nj * 16 + b_r;
                uint32_t ad = smem_u32(sBh + row * SKP + kh + b_c);
                LDSM_X4(bh[2 * nj][0], bh[2 * nj][1], bh[2 * nj + 1][0], bh[2 * nj + 1][1], ad);
                ad = smem_u32(sBl + row * SKP + kh + b_c);
                LDSM_X4(bl[2 * nj][0], bl[2 * nj][1], bl[2 * nj + 1][0], bl[2 * nj + 1][1], ad);
            }
            #pragma unroll
            for (int mi = 0; mi < 4; mi++)
                #pragma unroll
                for (int ni = 0; ni < 4; ni++) {
                    MMA_BF16(acc[mi][ni], ah[mi], bh[ni]);
                    MMA_BF16(acc[mi][ni], ah[mi], bl[ni]);
                    MMA_BF16(acc[mi][ni], al[mi], bh[ni]);
                }
        }
        __syncthreads();
    }

    // per-thread column attention-vector values (same cols for all mi)
    float vs0[4], vs1[4], vd0[4], vd1[4];
    #pragma unroll
    for (int ni = 0; ni < 4; ni++) {
        int c = n0 + wn * 32 + ni * 8 + ((lane & 3) << 1);
        vs0[ni] = (c < OUT_C) ? __ldg(a_src + c) : 0.f;
        vs1[ni] = (c + 1 < OUT_C) ? __ldg(a_src + c + 1) : 0.f;
        vd0[ni] = (c < OUT_C) ? __ldg(a_dst + c) : 0.f;
        vd1[ni] = (c + 1 < OUT_C) ? __ldg(a_dst + c + 1) : 0.f;
    }

    #pragma unroll
    for (int mi = 0; mi < 4; mi++) {
        int r = bm + wm * 64 + mi * 16 + (lane >> 2);
        // h store
        #pragma unroll
        for (int ni = 0; ni < 4; ni++) {
            int c = n0 + wn * 32 + ni * 8 + ((lane & 3) << 1);
            if (c >= OUT_C) continue;
            if (r < M)
                *(float2*)(g_h + (size_t)r * OUT_C + c) =
                    make_float2(acc[mi][ni][0], acc[mi][ni][1]);
            if (r + 8 < M)
                *(float2*)(g_h + (size_t)(r + 8) * OUT_C + c) =
                    make_float2(acc[mi][ni][2], acc[mi][ni][3]);
        }
        // fused alpha partials (rows r and r+8)
        float ps0 = 0.f, pd0 = 0.f, ps1 = 0.f, pd1 = 0.f;
        #pragma unroll
        for (int ni = 0; ni < 4; ni++) {
            ps0 += acc[mi][ni][0] * vs0[ni] + acc[mi][ni][1] * vs1[ni];
            pd0 += acc[mi][ni][0] * vd0[ni] + acc[mi][ni][1] * vd1[ni];
            ps1 += acc[mi][ni][2] * vs0[ni] + acc[mi][ni][3] * vs1[ni];
            pd1 += acc[mi][ni][2] * vd0[ni] + acc[mi][ni][3] * vd1[ni];
        }
        #pragma unroll
        for (int o = 1; o <= 2; o <<= 1) {
            ps0 += __shfl_xor_sync(0xffffffffu, ps0, o);
            pd0 += __shfl_xor_sync(0xffffffffu, pd0, o);
            ps1 += __shfl_xor_sync(0xffffffffu, ps1, o);
            pd1 += __shfl_xor_sync(0xffffffffu, pd1, o);
        }
        if ((lane & 3) == 0) {
            if (r < M) { atomicAdd(&g_as[r], ps0); atomicAdd(&g_ad[r], pd0); }
            if (r + 8 < M) { atomicAdd(&g_as[r + 8], ps1); atomicAdd(&g_ad[r + 8], pd1); }
        }
    }
}

// ---------------- passA / passB ----------------------------------------------
__global__ void passA_kernel(int Etot) {
    int i = blockIdx.x * blockDim.x + threadIdx.x;
    if (i >= Etot) return;
    int src = g_csr_src[i];
    int dst = g_csr_dst[i];
    float e = __ldg(&g_as[src]) + __ldg(&g_ad[dst]);
    e = (e > 0.f) ? e : NEG_SLOPE * e;
    g_e_csr[i] = __expf(e);
}

__global__ void passB_kernel(int n) {
    int w = (int)((blockIdx.x * (size_t)blockDim.x + threadIdx.x) >> 5);
    int lane = threadIdx.x & 31;
    if (w >= n) return;
    int off = g_off[w], deg = g_deg[w];
    float s = 0.f;
    for (int i = lane; i < deg; i += 32) s += g_e_csr[off + i];
    #pragma unroll
    for (int o = 16; o; o >>= 1) s += __shfl_xor_sync(0xffffffffu, s, o);
    if (lane == 0) g_s[w] = __frcp_rn(s);
}

// ---------------- passC layer 1: aggregate + bias + relu -> bf16 hi/lo -------
// 56 threads per dst: c<50 compute chunk, c in [50,56) zero-fill pad cols.
__global__ __launch_bounds__(896)
void passC_bf16_kernel(int n, const float* __restrict__ bias) {
    int t = blockIdx.x * 896 + threadIdx.x;
    int d = t / 56;
    int c = t % 56;
    if (d >= n) return;
    size_t base = (size_t)d * KP1 + c * 4;
    if (c >= 50) {
        *(uint2*)(g_ahi + base) = make_uint2(0, 0);
        *(uint2*)(g_alo + base) = make_uint2(0, 0);
        return;
    }
    float rs = __ldg(&g_s[d]);
    int off = g_off[d], deg = g_deg[d];
    float4 acc = __ldg((const float4*)bias + c);
    const float4* h4 = (const float4*)g_h;
    for (int j = 0; j < deg; j++) {
        int pos = off + j;
        float a = __ldg(&g_e_csr[pos]) * rs;
        int src = __ldg(&g_csr_src[pos]);
        float4 v = __ldg(h4 + (size_t)src * (OUT_C / 4) + c);
        acc.x = fmaf(a, v.x, acc.x);
        acc.y = fmaf(a, v.y, acc.y);
        acc.z = fmaf(a, v.z, acc.z);
        acc.w = fmaf(a, v.w, acc.w);
    }
    acc.x = fmaxf(acc.x, 0.f); acc.y = fmaxf(acc.y, 0.f);
    acc.z = fmaxf(acc.z, 0.f); acc.w = fmaxf(acc.w, 0.f);
    // split to bf16 hi/lo
    __nv_bfloat162 h01 = __floats2bfloat162_rn(acc.x, acc.y);
    __nv_bfloat162 h23 = __floats2bfloat162_rn(acc.z, acc.w);
    float2 b01 = __bfloat1622float2(h01);
    float2 b23 = __bfloat1622float2(h23);
    __nv_bfloat162 l01 = __floats2bfloat162_rn(acc.x - b01.x, acc.y - b01.y);
    __nv_bfloat162 l23 = __floats2bfloat162_rn(acc.z - b23.x, acc.w - b23.y);
    uint2 uh, ul;
    uh.x = *(uint32_t*)&h01; uh.y = *(uint32_t*)&h23;
    ul.x = *(uint32_t*)&l01; ul.y = *(uint32_t*)&l23;
    *(uint2*)(g_ahi + base) = uh;
    *(uint2*)(g_alo + base) = ul;
}

// ---------------- passC layer 2: aggregate + bias + relu -> fp32 out ---------
__global__ __launch_bounds__(800)
void passC_f32_kernel(int n, float* __restrict__ out,
                      const float* __restrict__ bias) {
    int t = blockIdx.x * 800 + threadIdx.x;
    int d = t / 50;
    int c = t % 50;
    if (d >= n) return;
    float rs = __ldg(&g_s[d]);
    int off = g_off[d], deg = g_deg[d];
    float4 acc = __ldg((const float4*)bias + c);
    const float4* h4 = (const float4*)g_h;
    for (int j = 0; j < deg; j++) {
        int pos = off + j;
        float a = __ldg(&g_e_csr[pos]) * rs;
        int src = __ldg(&g_csr_src[pos]);
        float4 v = __ldg(h4 + (size_t)src * (OUT_C / 4) + c);
        acc.x = fmaf(a, v.x, acc.x);
        acc.y = fmaf(a, v.y, acc.y);
        acc.z = fmaf(a, v.z, acc.z);
        acc.w = fmaf(a, v.w, acc.w);
    }
    acc.x = fmaxf(acc.x, 0.f); acc.y = fmaxf(acc.y, 0.f);
    acc.z = fmaxf(acc.z, 0.f); acc.w = fmaxf(acc.w, 0.f);
    ((float4*)out)[(size_t)d * (OUT_C / 4) + c] = acc;
}

// ---------------- launch -----------------------------------------------------
extern "C" void kernel_launch(void* const* d_in, const int* in_sizes, int n_in,
                              void* d_out, int out_size) {
    const float* x      = (const float*)d_in[0];
    const float* W0     = (const float*)d_in[1];
    const float* a_src0 = (const float*)d_in[2];
    const float* a_dst0 = (const float*)d_in[3];
    const float* b0     = (const float*)d_in[4];
    const float* W1     = (const float*)d_in[5];
    const float* a_src1 = (const float*)d_in[6];
    const float* a_dst1 = (const float*)d_in[7];
    const float* b1     = (const float*)d_in[8];
    const void*  ei     = d_in[9];

    int n    = in_sizes[0] / IN_C;   // 100000
    int E    = in_sizes[9] / 2;      // 1600000
    int Etot = E + n;

    cudaFuncSetAttribute(gemm_tc_kernel,
                         cudaFuncAttributeMaxDynamicSharedMemorySize, GEMM_SMEM);

    dim3 gemm_grid((n + 127) / 128, 2);
    int node_blocks  = (n + 255) / 256;
    int edge_blocks  = (Etot + 511) / 512;
    int scan_blocks  = (n + 1023) / 1024;
    int warp_blocks  = (int)(((long long)n * 32 + 255) / 256);
    int aggC1_blocks = (int)(((long long)n * 56 + 895) / 896);
    int aggC2_blocks = (int)(((long long)n * 50 + 799) / 800);
    int sa0_blocks   = (int)(((size_t)n * KP0 + 511) / 512);

    // ----- layer 1 front (gemm is 4th launch -> ncu capture) -----
    zero_asad_kernel<<<node_blocks, 256>>>(n);
    split_a_kernel<<<sa0_blocks, 512>>>(x, n, IN_C, KP0);
    split_w_kernel<<<(NPAD * KP0 + 255) / 256, 256>>>(W0, IN_C, KP0);
    gemm_tc_kernel<<<gemm_grid, 256, GEMM_SMEM>>>(n, KP0, KP0 / 32, a_src0, a_dst0);

    // ----- CSR build (overlap-able with gemm results not needed yet) -----
    probe_kernel<<<1, 32>>>((const int*)ei);
    zero_deg_kernel<<<node_blocks, 256>>>(n);
    hist_kernel<<<edge_blocks, 512>>>(ei, E, Etot);
    scan1_kernel<<<scan_blocks, 1024>>>(n);
    scan2_kernel<<<1, 128>>>(scan_blocks);
    scan3_kernel<<<node_blocks, 256>>>(n);
    fill_kernel<<<edge_blocks, 512>>>(ei, E, Etot);

    // ----- layer 1 back -----
    passA_kernel<<<edge_blocks, 512>>>(Etot);
    passB_kernel<<<warp_blocks, 256>>>(n);
    passC_bf16_kernel<<<aggC1_blocks, 896>>>(n, b0);

    // ----- layer 2 -----
    zero_asad_kernel<<<node_blocks, 256>>>(n);
    split_w_kernel<<<(NPAD * KP1 + 255) / 256, 256>>>(W1, OUT_C, KP1);
    gemm_tc_kernel<<<gemm_grid, 256, GEMM_SMEM>>>(n, KP1, KP1 / 32, a_src1, a_dst1);
    passA_kernel<<<edge_blocks, 512>>>(Etot);
    passB_kernel<<<warp_blocks, 256>>>(n);
    passC_f32_kernel<<<aggC2_blocks, 800>>>(n, (float*)d_out, b1);
}